// round 7
// baseline (speedup 1.0000x reference)
#include <cuda_runtime.h>
#include <cstdint>

#define Tn 512
#define Bn 128
#define Hn 256
#define Gn 1024
#define NBLK 128

typedef unsigned long long u64t;

// ---------------- device scratch ----------------
__device__ float g_pre0[(size_t)Tn * Gn * Bn];   // [t][gatecol][b]
__device__ float g_h0[2][Hn * Bn];               // [pp][h][b]
__device__ float g_h1[2][Hn * Bn];
__device__ __align__(16) unsigned g_flags[NBLK];

__device__ __forceinline__ float fsig(float x) {
    return __fdividef(1.0f, 1.0f + __expf(-x));
}
__device__ __forceinline__ float ftanh2(float x) {
    float e = __expf(2.0f * x);
    return 1.0f - __fdividef(2.0f, e + 1.0f);
}
__device__ __forceinline__ void ffma2(u64t& d, u64t a, u64t b) {
    asm volatile("fma.rn.f32x2 %0, %1, %2, %0;" : "+l"(d) : "l"(a), "l"(b));
}
__device__ __forceinline__ u64t dup2(float w) {
    u64t r;
    asm("mov.b64 %0, {%1, %1};" : "=l"(r) : "f"(w));
    return r;
}
__device__ __forceinline__ u64t pack2(float a, float b) {
    u64t r;
    asm("mov.b64 %0, {%1, %2};" : "=l"(r) : "f"(a), "f"(b));
    return r;
}
__device__ __forceinline__ float2 unpack2(u64t v) {
    float2 r;
    asm("mov.b64 {%0, %1}, %2;" : "=f"(r.x), "=f"(r.y) : "l"(v));
    return r;
}
__device__ __forceinline__ u64t addx2(u64t a, u64t b) {
    u64t r;
    asm("add.rn.f32x2 %0, %1, %2;" : "=l"(r) : "l"(a), "l"(b));
    return r;
}
__device__ __forceinline__ void cp16(void* dst, const float* src) {
    unsigned d = (unsigned)__cvta_generic_to_shared(dst);
    asm volatile("cp.async.cg.shared.global [%0], [%1], 16;" :: "r"(d), "l"(src));
}

// ---------------------------------------------------------------------------
// Init: zero h ping-pong buffers and flags (fresh every replay)
// ---------------------------------------------------------------------------
__global__ void zero_kernel() {
    int idx = blockIdx.x * 512 + threadIdx.x;    // 128 x 512 = 65536 exactly
    reinterpret_cast<float*>(g_h0)[idx] = 0.f;
    reinterpret_cast<float*>(g_h1)[idx] = 0.f;
    if (idx < NBLK) g_flags[idx] = 0u;
}

// ---------------------------------------------------------------------------
// Precompute: pre0[t][g][b] = b_ih0[g]+b_hh0[g] + sum_k x[t][b][k]*W_ih0[g][k]
// ---------------------------------------------------------------------------
__global__ __launch_bounds__(256) void precompute_kernel(
    const float* __restrict__ x, const float* __restrict__ W_ih,
    const float* __restrict__ b_ih, const float* __restrict__ b_hh)
{
    __shared__ __align__(16) u64t Xs[32][34];    // [k][bpair]
    __shared__ __align__(16) u64t Ws[32][130];   // [k][g] dup'd
    const int gt = blockIdx.x;
    const int bt = blockIdx.y;
    const int t  = blockIdx.z;
    const int tid = threadIdx.x;
    const int gy = tid >> 4;
    const int bx = tid & 15;

    const float* xb = x + ((size_t)t * Bn + bt * 64) * Hn;
    const float* wb = W_ih + (size_t)(gt * 128) * Hn;

    u64t acc[8][2];
#pragma unroll
    for (int i = 0; i < 8; i++) { acc[i][0] = 0ull; acc[i][1] = 0ull; }

    for (int kc = 0; kc < Hn; kc += 32) {
        {
            int bp = tid & 31;
            int k4 = (tid >> 5) * 4;
            const float* r0 = xb + (size_t)(2 * bp) * Hn + kc + k4;
            float4 a = *reinterpret_cast<const float4*>(r0);
            float4 b4 = *reinterpret_cast<const float4*>(r0 + Hn);
            Xs[k4 + 0][bp] = pack2(a.x, b4.x);
            Xs[k4 + 1][bp] = pack2(a.y, b4.y);
            Xs[k4 + 2][bp] = pack2(a.z, b4.z);
            Xs[k4 + 3][bp] = pack2(a.w, b4.w);
        }
#pragma unroll
        for (int j = 0; j < 4; j++) {
            int s = tid + j * 256;
            int g = s & 127;
            int k4 = (s >> 7) * 4;
            float4 w = *reinterpret_cast<const float4*>(wb + (size_t)g * Hn + kc + k4);
            Ws[k4 + 0][g] = dup2(w.x);
            Ws[k4 + 1][g] = dup2(w.y);
            Ws[k4 + 2][g] = dup2(w.z);
            Ws[k4 + 3][g] = dup2(w.w);
        }
        __syncthreads();
#pragma unroll
        for (int kk = 0; kk < 32; kk++) {
            ulonglong2 hv = *reinterpret_cast<const ulonglong2*>(&Xs[kk][bx * 2]);
            ulonglong2 w01 = *reinterpret_cast<const ulonglong2*>(&Ws[kk][gy * 8]);
            ulonglong2 w23 = *reinterpret_cast<const ulonglong2*>(&Ws[kk][gy * 8 + 2]);
            ulonglong2 w45 = *reinterpret_cast<const ulonglong2*>(&Ws[kk][gy * 8 + 4]);
            ulonglong2 w67 = *reinterpret_cast<const ulonglong2*>(&Ws[kk][gy * 8 + 6]);
            ffma2(acc[0][0], hv.x, w01.x); ffma2(acc[0][1], hv.y, w01.x);
            ffma2(acc[1][0], hv.x, w01.y); ffma2(acc[1][1], hv.y, w01.y);
            ffma2(acc[2][0], hv.x, w23.x); ffma2(acc[2][1], hv.y, w23.x);
            ffma2(acc[3][0], hv.x, w23.y); ffma2(acc[3][1], hv.y, w23.y);
            ffma2(acc[4][0], hv.x, w45.x); ffma2(acc[4][1], hv.y, w45.x);
            ffma2(acc[5][0], hv.x, w45.y); ffma2(acc[5][1], hv.y, w45.y);
            ffma2(acc[6][0], hv.x, w67.x); ffma2(acc[6][1], hv.y, w67.x);
            ffma2(acc[7][0], hv.x, w67.y); ffma2(acc[7][1], hv.y, w67.y);
        }
        __syncthreads();
    }
#pragma unroll
    for (int gi = 0; gi < 8; gi++) {
        int g = gt * 128 + gy * 8 + gi;
        float bias = __ldg(b_ih + g) + __ldg(b_hh + g);
        float2 lo = unpack2(acc[gi][0]);
        float2 hi = unpack2(acc[gi][1]);
        float4 v = make_float4(lo.x + bias, lo.y + bias, hi.x + bias, hi.y + bias);
        *reinterpret_cast<float4*>(g_pre0 + (size_t)t * (Gn * Bn)
            + (size_t)g * Bn + bt * 64 + bx * 4) = v;
    }
}

// ---------------------------------------------------------------------------
// Persistent skewed recurrence. 128 CTAs x 512 threads.
// CTA: bh = blk&1 (batch half), cg = blk>>1 (4 h-cols of both layers).
// Warps: bsel = w&3 (16-batch slice), kshi = w>>2 (64-K slice).
// Lanes: cs = lane&7 (2 col-pairs: pairs 2cs,2cs+1), kslo = lane>>3 (16-K sub).
// One flag barrier per iteration, 2 block syncs, warp-private cp.async staging.
// smem: WsA float[256][32] 32K | WsB float[256][16] 16K |
//       stage 16w x (A 4160 + B 4160) = 133120 | part 32 x 1184 = 37888
// ---------------------------------------------------------------------------
#define SM_WA    0
#define SM_WB    32768
#define SM_STAGE 49152
#define SM_PART  182272
#define SMEM_TOTAL 220160

__global__ __launch_bounds__(512, 1) void lstm_persistent(
    const float* __restrict__ W_ih, const float* __restrict__ W_hh,
    const float* __restrict__ b_ih, const float* __restrict__ b_hh,
    float* __restrict__ out)
{
    extern __shared__ __align__(16) char smraw[];
    char* smWA   = smraw + SM_WA;
    char* smWB   = smraw + SM_WB;
    char* stage  = smraw + SM_STAGE;
    char* partc  = smraw + SM_PART;

    const int tid  = threadIdx.x;
    const int blk  = blockIdx.x;
    const int bh   = blk & 1;
    const int cg   = blk >> 1;
    const int w    = tid >> 5;
    const int lane = tid & 31;
    const int bsel = w & 3;           // 16-batch slice
    const int kshi = w >> 2;          // 0..3 (64 k)
    const int cs   = lane & 7;        // col-pair group (pairs 2cs, 2cs+1)
    const int kslo = lane >> 3;       // 0..3 (16 k)

    // ---- weights into smem (plain floats, once) ----
    {
        // WsA rows: [k][pair p: (Whh0[gc(p)][k], Wih1[gc(p)][k])], 32 floats/row
        int p  = tid & 15;
        int kg = tid >> 4;            // 0..31
        int gc = (p >> 2) * Hn + cg * 4 + (p & 3);
        const float* wh0 = W_hh + (size_t)gc * Hn;
        const float* wi1 = W_ih + (size_t)Gn * Hn + (size_t)gc * Hn;
        float* WA = reinterpret_cast<float*>(smWA);
#pragma unroll
        for (int j = 0; j < 8; j++) {
            int k = kg * 8 + j;
            WA[k * 32 + p * 2 + 0] = __ldg(wh0 + k);
            WA[k * 32 + p * 2 + 1] = __ldg(wi1 + k);
        }
        // WsB rows: [k][c: (Whh1[gc(2c)][k], Whh1[gc(2c+1)][k])], 16 floats/row
        int c   = tid & 7;
        int kg2 = tid >> 3;           // 0..63
        int gcA = ((2 * c) >> 2) * Hn + cg * 4 + ((2 * c) & 3);
        int gcB = ((2 * c + 1) >> 2) * Hn + cg * 4 + ((2 * c + 1) & 3);
        const float* wh1a = W_hh + (size_t)Gn * Hn + (size_t)gcA * Hn;
        const float* wh1b = W_hh + (size_t)Gn * Hn + (size_t)gcB * Hn;
        float* WB = reinterpret_cast<float*>(smWB);
#pragma unroll
        for (int j = 0; j < 4; j++) {
            int k = kg2 * 4 + j;
            WB[k * 16 + c * 2 + 0] = __ldg(wh1a + k);
            WB[k * 16 + c * 2 + 1] = __ldg(wh1b + k);
        }
    }
    // elementwise identity (EW0: tid<256, EW1: tid>=256)
    const int hcl = (tid >> 6) & 3;
    const int bl  = tid & 63;
    const int hcol = cg * 4 + hcl;
    const int b = bh * 64 + bl;
    float b1s[4];
#pragma unroll
    for (int g = 0; g < 4; g++)
        b1s[g] = __ldg(b_ih + Gn + g * Hn + hcol) + __ldg(b_hh + Gn + g * Hn + hcol);

    // per-warp staging pointers (kslo-padded layout: 4 blocks of 1040B each)
    char* myStA = stage + w * 8320;
    char* myStB = myStA + 4160;

    float creg = 0.f;

    const size_t OUT_H = (size_t)Tn * Bn * Hn;
    const size_t OUT_C = OUT_H + 2 * (size_t)Bn * Hn;

    __syncthreads();   // weights visible

    for (int i = 0; i <= Tn; i++) {
        const int rslot = (i & 1) ^ 1;
        const int wslot = i & 1;

        // ===== flag barrier: wait until all CTAs finished iter i-1 =====
        if (i > 0) {
            const uint4* f4 = reinterpret_cast<const uint4*>(g_flags);
            const unsigned tgt = (unsigned)i;
            for (;;) {
                uint4 v = __ldcg(f4 + lane);
                if (v.x >= tgt && v.y >= tgt && v.z >= tgt && v.w >= tgt) break;
                __nanosleep(40);
            }
            __syncwarp();
            __threadfence();   // acquire
        }

        const float* hA = g_h0[rslot];
        const float* hB = g_h1[rslot];

        // ===== warp-private staging (A then B), kslo-padded =====
#pragma unroll
        for (int j = 0; j < 8; j++) {
            int f = lane + j * 32;
            int ksb = f >> 6, rem = f & 63;
            int krow = rem >> 2, seg = rem & 3;
            int k = kshi * 64 + ksb * 16 + krow;
            size_t so = (size_t)k * Bn + bh * 64 + bsel * 16 + seg * 4;
            cp16(myStA + ksb * 1040 + krow * 64 + seg * 16, hA + so);
        }
        asm volatile("cp.async.commit_group;");
#pragma unroll
        for (int j = 0; j < 8; j++) {
            int f = lane + j * 32;
            int ksb = f >> 6, rem = f & 63;
            int krow = rem >> 2, seg = rem & 3;
            int k = kshi * 64 + ksb * 16 + krow;
            size_t so = (size_t)k * Bn + bh * 64 + bsel * 16 + seg * 4;
            cp16(myStB + ksb * 1040 + krow * 64 + seg * 16, hB + so);
        }
        asm volatile("cp.async.commit_group;");

        // prefetch pre0 gates (EW0 operand) while staging flies
        float pg[4] = {0.f, 0.f, 0.f, 0.f};
        if (tid < 256 && i < Tn) {
            const float* pb = g_pre0 + (size_t)i * (Gn * Bn);
#pragma unroll
            for (int g = 0; g < 4; g++)
                pg[g] = __ldg(pb + (size_t)(g * Hn + hcol) * Bn + b);
        }

        // acc[0]=pair0-L0, acc[1]=pair1-L0, acc[2]=pair0-L1, acc[3]=pair1-L1
        u64t acc[4][8];
#pragma unroll
        for (int r = 0; r < 4; r++)
#pragma unroll
            for (int j = 0; j < 8; j++) acc[r][j] = 0ull;

        asm volatile("cp.async.wait_group 1;");
        __syncwarp();
        // ===== phase A: L0-rec + L1-input on h0 slice =====
        {
            const char* hp = myStA + kslo * 1040;
            const char* wp = smWA + (size_t)(kshi * 64 + kslo * 16) * 128 + cs * 16;
#pragma unroll 4
            for (int u = 0; u < 16; u++) {
                ulonglong2 h0v = *reinterpret_cast<const ulonglong2*>(hp);
                ulonglong2 h1v = *reinterpret_cast<const ulonglong2*>(hp + 16);
                ulonglong2 h2v = *reinterpret_cast<const ulonglong2*>(hp + 32);
                ulonglong2 h3v = *reinterpret_cast<const ulonglong2*>(hp + 48);
                float4 wv = *reinterpret_cast<const float4*>(wp);
                u64t w0a = dup2(wv.x), w1a = dup2(wv.y);
                u64t w0b = dup2(wv.z), w1b = dup2(wv.w);
                u64t hh[8] = {h0v.x, h0v.y, h1v.x, h1v.y, h2v.x, h2v.y, h3v.x, h3v.y};
#pragma unroll
                for (int j = 0; j < 8; j++) {
                    ffma2(acc[0][j], hh[j], w0a);
                    ffma2(acc[2][j], hh[j], w1a);
                    ffma2(acc[1][j], hh[j], w0b);
                    ffma2(acc[3][j], hh[j], w1b);
                }
                hp += 64; wp += 128;
            }
        }
        asm volatile("cp.async.wait_group 0;");
        __syncwarp();
        // ===== phase B: L1-rec on h1 slice (accumulate into L1 accs) =====
        {
            const char* hp = myStB + kslo * 1040;
            const char* wp = smWB + (size_t)(kshi * 64 + kslo * 16) * 64 + cs * 8;
#pragma unroll 4
            for (int u = 0; u < 16; u++) {
                ulonglong2 h0v = *reinterpret_cast<const ulonglong2*>(hp);
                ulonglong2 h1v = *reinterpret_cast<const ulonglong2*>(hp + 16);
                ulonglong2 h2v = *reinterpret_cast<const ulonglong2*>(hp + 32);
                ulonglong2 h3v = *reinterpret_cast<const ulonglong2*>(hp + 48);
                float2 wv = *reinterpret_cast<const float2*>(wp);
                u64t w2a = dup2(wv.x), w2b = dup2(wv.y);
                u64t hh[8] = {h0v.x, h0v.y, h1v.x, h1v.y, h2v.x, h2v.y, h3v.x, h3v.y};
#pragma unroll
                for (int j = 0; j < 8; j++) {
                    ffma2(acc[2][j], hh[j], w2a);
                    ffma2(acc[3][j], hh[j], w2b);
                }
                hp += 64; wp += 64;
            }
        }

        // ===== in-warp reduce over kslo (xor 8, xor 16) =====
#pragma unroll
        for (int r = 0; r < 4; r++)
#pragma unroll
            for (int j = 0; j < 8; j++) {
                u64t v = acc[r][j];
                v = addx2(v, (u64t)__shfl_xor_sync(0xFFFFFFFFu, v, 8));
                v = addx2(v, (u64t)__shfl_xor_sync(0xFFFFFFFFu, v, 16));
                acc[r][j] = v;
            }
        if (kslo == 0) {
#pragma unroll
            for (int r = 0; r < 4; r++) {
                int row = (r < 2) ? (2 * cs + r) : (16 + 2 * cs + (r - 2));
                char* pb = partc + row * 1184 + kshi * 288 + bsel * 64;
                reinterpret_cast<ulonglong2*>(pb)[0] = make_ulonglong2(acc[r][0], acc[r][1]);
                reinterpret_cast<ulonglong2*>(pb)[1] = make_ulonglong2(acc[r][2], acc[r][3]);
                reinterpret_cast<ulonglong2*>(pb)[2] = make_ulonglong2(acc[r][4], acc[r][5]);
                reinterpret_cast<ulonglong2*>(pb)[3] = make_ulonglong2(acc[r][6], acc[r][7]);
            }
        }
        __syncthreads();

        // ===== elementwise =====
        if (tid < 256) {
            if (i < Tn) {
                float s[4];
#pragma unroll
                for (int g = 0; g < 4; g++) {
                    const float* pr = reinterpret_cast<const float*>(
                        partc + (g * 4 + hcl) * 1184 + bl * 4);
                    s[g] = pg[g] + pr[0] + pr[72] + pr[144] + pr[216];
                }
                float cn = fsig(s[1]) * creg + fsig(s[0]) * ftanh2(s[2]);
                creg = cn;
                float hn = fsig(s[3]) * ftanh2(cn);
                __stcg(&g_h0[wslot][hcol * Bn + b], hn);
                if (i == Tn - 1) {
                    out[OUT_H + (size_t)b * Hn + hcol] = hn;
                    out[OUT_C + (size_t)b * Hn + hcol] = cn;
                }
            }
        } else {
            if (i >= 1) {
                const int t1 = i - 1;
                float s[4];
#pragma unroll
                for (int g = 0; g < 4; g++) {
                    const float* pr = reinterpret_cast<const float*>(
                        partc + (16 + g * 4 + hcl) * 1184 + bl * 4);
                    s[g] = b1s[g] + pr[0] + pr[72] + pr[144] + pr[216];
                }
                float cn = fsig(s[1]) * creg + fsig(s[0]) * ftanh2(s[2]);
                creg = cn;
                float hn = fsig(s[3]) * ftanh2(cn);
                __stcg(&g_h1[wslot][hcol * Bn + b], hn);
                out[(size_t)t1 * (Bn * Hn) + (size_t)b * Hn + hcol] = hn;
                if (i == Tn) {
                    out[OUT_H + (size_t)Bn * Hn + (size_t)b * Hn + hcol] = hn;
                    out[OUT_C + (size_t)Bn * Hn + (size_t)b * Hn + hcol] = cn;
                }
            }
        }
        __syncthreads();
        if (tid == 0) {
            __threadfence();
            __stcg(&g_flags[blk], (unsigned)(i + 1));
        }
    }
}

extern "C" void kernel_launch(void* const* d_in, const int* in_sizes, int n_in,
                              void* d_out, int out_size) {
    (void)in_sizes; (void)n_in; (void)out_size;
    const float* x    = (const float*)d_in[0];
    const float* W_ih = (const float*)d_in[1];
    const float* W_hh = (const float*)d_in[2];
    const float* b_ih = (const float*)d_in[3];
    const float* b_hh = (const float*)d_in[4];
    float* out = (float*)d_out;

    cudaFuncSetAttribute(lstm_persistent,
                         cudaFuncAttributeMaxDynamicSharedMemorySize, SMEM_TOTAL);

    zero_kernel<<<NBLK, 512>>>();
    dim3 gPre(8, 2, 512);
    precompute_kernel<<<gPre, 256>>>(x, W_ih, b_ih, b_hh);
    lstm_persistent<<<NBLK, 512, SMEM_TOTAL>>>(W_ih, W_hh, b_ih, b_hh, out);
}

// round 8
// speedup vs baseline: 3.2033x; 3.2033x over previous
#include <cuda_runtime.h>
#include <cstdint>

#define Tn 512
#define Bn 128
#define Hn 256
#define Gn 1024
#define NBLK 128

typedef unsigned long long u64t;

// ---------------- device scratch ----------------
__device__ float g_pre0[(size_t)Tn * Gn * Bn];   // [t][gatecol][b]
__device__ float g_h0[2][Hn * Bn];               // [pp][h][b]
__device__ float g_h1[2][Hn * Bn];
__device__ volatile unsigned g_bar_gen = 0;
__device__ unsigned g_bar_cnt = 0;

__device__ __forceinline__ float fsig(float x) {
    return __fdividef(1.0f, 1.0f + __expf(-x));
}
__device__ __forceinline__ float ftanh2(float x) {
    float e = __expf(2.0f * x);
    return 1.0f - __fdividef(2.0f, e + 1.0f);
}
__device__ __forceinline__ void grid_barrier() {
    __threadfence();        // release all threads' prior global writes
    __syncthreads();
    if (threadIdx.x == 0) {
        unsigned gen = g_bar_gen;
        if (atomicAdd(&g_bar_cnt, 1u) == (unsigned)(NBLK - 1)) {
            g_bar_cnt = 0u;
            __threadfence();
            g_bar_gen = gen + 1u;
        } else {
            while (g_bar_gen == gen) { __nanosleep(40); }
            __threadfence();
        }
    }
    __syncthreads();
}
__device__ __forceinline__ void ffma2(u64t& d, u64t a, u64t b) {
    asm volatile("fma.rn.f32x2 %0, %1, %2, %0;" : "+l"(d) : "l"(a), "l"(b));
}
__device__ __forceinline__ u64t dup2(float w) {
    u64t r;
    asm("mov.b64 %0, {%1, %1};" : "=l"(r) : "f"(w));
    return r;
}
__device__ __forceinline__ u64t pack2(float a, float b) {
    u64t r;
    asm("mov.b64 %0, {%1, %2};" : "=l"(r) : "f"(a), "f"(b));
    return r;
}
__device__ __forceinline__ float2 unpack2(u64t v) {
    float2 r;
    asm("mov.b64 {%0, %1}, %2;" : "=f"(r.x), "=f"(r.y) : "l"(v));
    return r;
}
__device__ __forceinline__ u64t addx2(u64t a, u64t b) {
    u64t r;
    asm("add.rn.f32x2 %0, %1, %2;" : "=l"(r) : "l"(a), "l"(b));
    return r;
}
__device__ __forceinline__ void cp16(void* dst, const float* src) {
    unsigned d = (unsigned)__cvta_generic_to_shared(dst);
    asm volatile("cp.async.cg.shared.global [%0], [%1], 16;" :: "r"(d), "l"(src));
}

// ---------------------------------------------------------------------------
// Precompute: pre0[t][g][b] = b_ih0[g]+b_hh0[g] + sum_k x[t][b][k]*W_ih0[g][k]
// ---------------------------------------------------------------------------
__global__ __launch_bounds__(256) void precompute_kernel(
    const float* __restrict__ x, const float* __restrict__ W_ih,
    const float* __restrict__ b_ih, const float* __restrict__ b_hh)
{
    __shared__ __align__(16) u64t Xs[32][34];    // [k][bpair]
    __shared__ __align__(16) u64t Ws[32][130];   // [k][g] dup'd
    const int gt = blockIdx.x;
    const int bt = blockIdx.y;
    const int t  = blockIdx.z;
    const int tid = threadIdx.x;
    const int gy = tid >> 4;
    const int bx = tid & 15;

    const float* xb = x + ((size_t)t * Bn + bt * 64) * Hn;
    const float* wb = W_ih + (size_t)(gt * 128) * Hn;

    u64t acc[8][2];
#pragma unroll
    for (int i = 0; i < 8; i++) { acc[i][0] = 0ull; acc[i][1] = 0ull; }

    for (int kc = 0; kc < Hn; kc += 32) {
        {
            int bp = tid & 31;
            int k4 = (tid >> 5) * 4;
            const float* r0 = xb + (size_t)(2 * bp) * Hn + kc + k4;
            float4 a = *reinterpret_cast<const float4*>(r0);
            float4 b4 = *reinterpret_cast<const float4*>(r0 + Hn);
            Xs[k4 + 0][bp] = pack2(a.x, b4.x);
            Xs[k4 + 1][bp] = pack2(a.y, b4.y);
            Xs[k4 + 2][bp] = pack2(a.z, b4.z);
            Xs[k4 + 3][bp] = pack2(a.w, b4.w);
        }
#pragma unroll
        for (int j = 0; j < 4; j++) {
            int s = tid + j * 256;
            int g = s & 127;
            int k4 = (s >> 7) * 4;
            float4 w = *reinterpret_cast<const float4*>(wb + (size_t)g * Hn + kc + k4);
            Ws[k4 + 0][g] = dup2(w.x);
            Ws[k4 + 1][g] = dup2(w.y);
            Ws[k4 + 2][g] = dup2(w.z);
            Ws[k4 + 3][g] = dup2(w.w);
        }
        __syncthreads();
#pragma unroll
        for (int kk = 0; kk < 32; kk++) {
            ulonglong2 hv = *reinterpret_cast<const ulonglong2*>(&Xs[kk][bx * 2]);
            ulonglong2 w01 = *reinterpret_cast<const ulonglong2*>(&Ws[kk][gy * 8]);
            ulonglong2 w23 = *reinterpret_cast<const ulonglong2*>(&Ws[kk][gy * 8 + 2]);
            ulonglong2 w45 = *reinterpret_cast<const ulonglong2*>(&Ws[kk][gy * 8 + 4]);
            ulonglong2 w67 = *reinterpret_cast<const ulonglong2*>(&Ws[kk][gy * 8 + 6]);
            ffma2(acc[0][0], hv.x, w01.x); ffma2(acc[0][1], hv.y, w01.x);
            ffma2(acc[1][0], hv.x, w01.y); ffma2(acc[1][1], hv.y, w01.y);
            ffma2(acc[2][0], hv.x, w23.x); ffma2(acc[2][1], hv.y, w23.x);
            ffma2(acc[3][0], hv.x, w23.y); ffma2(acc[3][1], hv.y, w23.y);
            ffma2(acc[4][0], hv.x, w45.x); ffma2(acc[4][1], hv.y, w45.x);
            ffma2(acc[5][0], hv.x, w45.y); ffma2(acc[5][1], hv.y, w45.y);
            ffma2(acc[6][0], hv.x, w67.x); ffma2(acc[6][1], hv.y, w67.x);
            ffma2(acc[7][0], hv.x, w67.y); ffma2(acc[7][1], hv.y, w67.y);
        }
        __syncthreads();
    }
#pragma unroll
    for (int gi = 0; gi < 8; gi++) {
        int g = gt * 128 + gy * 8 + gi;
        float bias = __ldg(b_ih + g) + __ldg(b_hh + g);
        float2 lo = unpack2(acc[gi][0]);
        float2 hi = unpack2(acc[gi][1]);
        float4 v = make_float4(lo.x + bias, lo.y + bias, hi.x + bias, hi.y + bias);
        *reinterpret_cast<float4*>(g_pre0 + (size_t)t * (Gn * Bn)
            + (size_t)g * Bn + bt * 64 + bx * 4) = v;
    }
}

// ---------------------------------------------------------------------------
// Persistent skewed recurrence. 128 CTAs x 512 threads.
// CTA: bh = blk&1 (batch half), cg = blk>>1 (4 h-cols of both layers).
// Warps: bsel = w&3 (16-batch slice), kshi = w>>2 (64-K slice).
// Lanes: cs = lane&7 (2 col-pairs), kslo = lane>>3 (16-K sub-slice).
// One atomic grid barrier per iteration, warp-private cp.async staging.
// ---------------------------------------------------------------------------
#define SM_WA    0
#define SM_WB    32768
#define SM_STAGE 49152
#define SM_PART  182272
#define SMEM_TOTAL 220160

__global__ __launch_bounds__(512, 1) void lstm_persistent(
    const float* __restrict__ W_ih, const float* __restrict__ W_hh,
    const float* __restrict__ b_ih, const float* __restrict__ b_hh,
    float* __restrict__ out)
{
    extern __shared__ __align__(16) char smraw[];
    char* smWA   = smraw + SM_WA;
    char* smWB   = smraw + SM_WB;
    char* stage  = smraw + SM_STAGE;
    char* partc  = smraw + SM_PART;

    const int tid  = threadIdx.x;
    const int blk  = blockIdx.x;
    const int bh   = blk & 1;
    const int cg   = blk >> 1;
    const int w    = tid >> 5;
    const int lane = tid & 31;
    const int bsel = w & 3;           // 16-batch slice
    const int kshi = w >> 2;          // 0..3 (64 k)
    const int cs   = lane & 7;        // col-pair group (pairs 2cs, 2cs+1)
    const int kslo = lane >> 3;       // 0..3 (16 k)

    // ---- weights into smem (plain floats, once) ----
    {
        int p  = tid & 15;
        int kg = tid >> 4;            // 0..31
        int gc = (p >> 2) * Hn + cg * 4 + (p & 3);
        const float* wh0 = W_hh + (size_t)gc * Hn;
        const float* wi1 = W_ih + (size_t)Gn * Hn + (size_t)gc * Hn;
        float* WA = reinterpret_cast<float*>(smWA);
#pragma unroll
        for (int j = 0; j < 8; j++) {
            int k = kg * 8 + j;
            WA[k * 32 + p * 2 + 0] = __ldg(wh0 + k);
            WA[k * 32 + p * 2 + 1] = __ldg(wi1 + k);
        }
        int c   = tid & 7;
        int kg2 = tid >> 3;           // 0..63
        int gcA = ((2 * c) >> 2) * Hn + cg * 4 + ((2 * c) & 3);
        int gcB = ((2 * c + 1) >> 2) * Hn + cg * 4 + ((2 * c + 1) & 3);
        const float* wh1a = W_hh + (size_t)Gn * Hn + (size_t)gcA * Hn;
        const float* wh1b = W_hh + (size_t)Gn * Hn + (size_t)gcB * Hn;
        float* WB = reinterpret_cast<float*>(smWB);
#pragma unroll
        for (int j = 0; j < 4; j++) {
            int k = kg2 * 4 + j;
            WB[k * 16 + c * 2 + 0] = __ldg(wh1a + k);
            WB[k * 16 + c * 2 + 1] = __ldg(wh1b + k);
        }
    }
    // elementwise identity (EW0: tid<256, EW1: tid>=256)
    const int hcl = (tid >> 6) & 3;
    const int bl  = tid & 63;
    const int hcol = cg * 4 + hcl;
    const int b = bh * 64 + bl;
    float b1s[4];
#pragma unroll
    for (int g = 0; g < 4; g++)
        b1s[g] = __ldg(b_ih + Gn + g * Hn + hcol) + __ldg(b_hh + Gn + g * Hn + hcol);

    // per-warp staging pointers (kslo-padded layout: 4 blocks of 1040B each)
    char* myStA = stage + w * 8320;
    char* myStB = myStA + 4160;

    // zero init h ping-pong buffers (both slots of both layers)
    {
        int idx = blk * 512 + tid;    // covers 2*32768 per array
        reinterpret_cast<float*>(g_h0)[idx] = 0.f;
        reinterpret_cast<float*>(g_h1)[idx] = 0.f;
    }
    float creg = 0.f;

    const size_t OUT_H = (size_t)Tn * Bn * Hn;
    const size_t OUT_C = OUT_H + 2 * (size_t)Bn * Hn;

    grid_barrier();   // init + weights visible

    for (int i = 0; i <= Tn; i++) {
        const int rslot = (i & 1) ^ 1;
        const int wslot = i & 1;
        const float* hA = g_h0[rslot];
        const float* hB = g_h1[rslot];

        // ===== warp-private staging (A then B), kslo-padded =====
#pragma unroll
        for (int j = 0; j < 8; j++) {
            int f = lane + j * 32;
            int ksb = f >> 6, rem = f & 63;
            int krow = rem >> 2, seg = rem & 3;
            int k = kshi * 64 + ksb * 16 + krow;
            size_t so = (size_t)k * Bn + bh * 64 + bsel * 16 + seg * 4;
            cp16(myStA + ksb * 1040 + krow * 64 + seg * 16, hA + so);
        }
        asm volatile("cp.async.commit_group;");
#pragma unroll
        for (int j = 0; j < 8; j++) {
            int f = lane + j * 32;
            int ksb = f >> 6, rem = f & 63;
            int krow = rem >> 2, seg = rem & 3;
            int k = kshi * 64 + ksb * 16 + krow;
            size_t so = (size_t)k * Bn + bh * 64 + bsel * 16 + seg * 4;
            cp16(myStB + ksb * 1040 + krow * 64 + seg * 16, hB + so);
        }
        asm volatile("cp.async.commit_group;");

        // prefetch pre0 gates (EW0 operand) while staging flies
        float pg[4] = {0.f, 0.f, 0.f, 0.f};
        if (tid < 256 && i < Tn) {
            const float* pb = g_pre0 + (size_t)i * (Gn * Bn);
#pragma unroll
            for (int g = 0; g < 4; g++)
                pg[g] = __ldg(pb + (size_t)(g * Hn + hcol) * Bn + b);
        }

        // acc[0]=pair0-L0, acc[1]=pair1-L0, acc[2]=pair0-L1, acc[3]=pair1-L1
        u64t acc[4][8];
#pragma unroll
        for (int r = 0; r < 4; r++)
#pragma unroll
            for (int j = 0; j < 8; j++) acc[r][j] = 0ull;

        asm volatile("cp.async.wait_group 1;");
        __syncwarp();
        // ===== phase A: L0-rec + L1-input on h0 slice =====
        {
            const char* hp = myStA + kslo * 1040;
            const char* wp = smWA + (size_t)(kshi * 64 + kslo * 16) * 128 + cs * 16;
#pragma unroll 4
            for (int u = 0; u < 16; u++) {
                ulonglong2 h0v = *reinterpret_cast<const ulonglong2*>(hp);
                ulonglong2 h1v = *reinterpret_cast<const ulonglong2*>(hp + 16);
                ulonglong2 h2v = *reinterpret_cast<const ulonglong2*>(hp + 32);
                ulonglong2 h3v = *reinterpret_cast<const ulonglong2*>(hp + 48);
                float4 wv = *reinterpret_cast<const float4*>(wp);
                u64t w0a = dup2(wv.x), w1a = dup2(wv.y);
                u64t w0b = dup2(wv.z), w1b = dup2(wv.w);
                u64t hh[8] = {h0v.x, h0v.y, h1v.x, h1v.y, h2v.x, h2v.y, h3v.x, h3v.y};
#pragma unroll
                for (int j = 0; j < 8; j++) {
                    ffma2(acc[0][j], hh[j], w0a);
                    ffma2(acc[2][j], hh[j], w1a);
                    ffma2(acc[1][j], hh[j], w0b);
                    ffma2(acc[3][j], hh[j], w1b);
                }
                hp += 64; wp += 128;
            }
        }
        asm volatile("cp.async.wait_group 0;");
        __syncwarp();
        // ===== phase B: L1-rec on h1 slice (accumulate into L1 accs) =====
        {
            const char* hp = myStB + kslo * 1040;
            const char* wp = smWB + (size_t)(kshi * 64 + kslo * 16) * 64 + cs * 8;
#pragma unroll 4
            for (int u = 0; u < 16; u++) {
                ulonglong2 h0v = *reinterpret_cast<const ulonglong2*>(hp);
                ulonglong2 h1v = *reinterpret_cast<const ulonglong2*>(hp + 16);
                ulonglong2 h2v = *reinterpret_cast<const ulonglong2*>(hp + 32);
                ulonglong2 h3v = *reinterpret_cast<const ulonglong2*>(hp + 48);
                float2 wv = *reinterpret_cast<const float2*>(wp);
                u64t w2a = dup2(wv.x), w2b = dup2(wv.y);
                u64t hh[8] = {h0v.x, h0v.y, h1v.x, h1v.y, h2v.x, h2v.y, h3v.x, h3v.y};
#pragma unroll
                for (int j = 0; j < 8; j++) {
                    ffma2(acc[2][j], hh[j], w2a);
                    ffma2(acc[3][j], hh[j], w2b);
                }
                hp += 64; wp += 64;
            }
        }

        // ===== in-warp reduce over kslo (xor 8, xor 16) =====
#pragma unroll
        for (int r = 0; r < 4; r++)
#pragma unroll
            for (int j = 0; j < 8; j++) {
                u64t v = acc[r][j];
                v = addx2(v, (u64t)__shfl_xor_sync(0xFFFFFFFFu, v, 8));
                v = addx2(v, (u64t)__shfl_xor_sync(0xFFFFFFFFu, v, 16));
                acc[r][j] = v;
            }
        if (kslo == 0) {
#pragma unroll
            for (int r = 0; r < 4; r++) {
                int row = (r < 2) ? (2 * cs + r) : (16 + 2 * cs + (r - 2));
                char* pb = partc + row * 1184 + kshi * 288 + bsel * 64;
                reinterpret_cast<ulonglong2*>(pb)[0] = make_ulonglong2(acc[r][0], acc[r][1]);
                reinterpret_cast<ulonglong2*>(pb)[1] = make_ulonglong2(acc[r][2], acc[r][3]);
                reinterpret_cast<ulonglong2*>(pb)[2] = make_ulonglong2(acc[r][4], acc[r][5]);
                reinterpret_cast<ulonglong2*>(pb)[3] = make_ulonglong2(acc[r][6], acc[r][7]);
            }
        }
        __syncthreads();

        // ===== elementwise =====
        if (tid < 256) {
            if (i < Tn) {
                float s[4];
#pragma unroll
                for (int g = 0; g < 4; g++) {
                    const float* pr = reinterpret_cast<const float*>(
                        partc + (g * 4 + hcl) * 1184 + bl * 4);
                    s[g] = pg[g] + pr[0] + pr[72] + pr[144] + pr[216];
                }
                float cn = fsig(s[1]) * creg + fsig(s[0]) * ftanh2(s[2]);
                creg = cn;
                float hn = fsig(s[3]) * ftanh2(cn);
                __stcg(&g_h0[wslot][hcol * Bn + b], hn);
                if (i == Tn - 1) {
                    out[OUT_H + (size_t)b * Hn + hcol] = hn;
                    out[OUT_C + (size_t)b * Hn + hcol] = cn;
                }
            }
        } else {
            if (i >= 1) {
                const int t1 = i - 1;
                float s[4];
#pragma unroll
                for (int g = 0; g < 4; g++) {
                    const float* pr = reinterpret_cast<const float*>(
                        partc + (16 + g * 4 + hcl) * 1184 + bl * 4);
                    s[g] = b1s[g] + pr[0] + pr[72] + pr[144] + pr[216];
                }
                float cn = fsig(s[1]) * creg + fsig(s[0]) * ftanh2(s[2]);
                creg = cn;
                float hn = fsig(s[3]) * ftanh2(cn);
                __stcg(&g_h1[wslot][hcol * Bn + b], hn);
                out[(size_t)t1 * (Bn * Hn) + (size_t)b * Hn + hcol] = hn;
                if (i == Tn) {
                    out[OUT_H + (size_t)Bn * Hn + (size_t)b * Hn + hcol] = hn;
                    out[OUT_C + (size_t)Bn * Hn + (size_t)b * Hn + hcol] = cn;
                }
            }
        }
        grid_barrier();
    }
}

extern "C" void kernel_launch(void* const* d_in, const int* in_sizes, int n_in,
                              void* d_out, int out_size) {
    (void)in_sizes; (void)n_in; (void)out_size;
    const float* x    = (const float*)d_in[0];
    const float* W_ih = (const float*)d_in[1];
    const float* W_hh = (const float*)d_in[2];
    const float* b_ih = (const float*)d_in[3];
    const float* b_hh = (const float*)d_in[4];
    float* out = (float*)d_out;

    cudaFuncSetAttribute(lstm_persistent,
                         cudaFuncAttributeMaxDynamicSharedMemorySize, SMEM_TOTAL);

    dim3 gPre(8, 2, 512);
    precompute_kernel<<<gPre, 256>>>(x, W_ih, b_ih, b_hh);
    lstm_persistent<<<NBLK, 512, SMEM_TOTAL>>>(W_ih, W_hh, b_ih, b_hh, out);
}

// round 9
// speedup vs baseline: 3.5156x; 1.0975x over previous
#include <cuda_runtime.h>
#include <cstdint>

#define Tn 512
#define Bn 128
#define Hn 256
#define Gn 1024
#define NBLK 128

typedef unsigned long long u64t;

// ---------------- device scratch ----------------
__device__ float g_pre0[(size_t)Tn * Gn * Bn];   // [t][gatecol][b]
__device__ float g_h0[2][Hn * Bn];               // [pp][h][b]
__device__ float g_h1[2][Hn * Bn];
__device__ volatile unsigned g_bar_gen = 0;
__device__ unsigned g_bar_cnt = 0;

__device__ __forceinline__ float fsig(float x) {
    return __fdividef(1.0f, 1.0f + __expf(-x));
}
__device__ __forceinline__ float ftanh2(float x) {
    float e = __expf(2.0f * x);
    return 1.0f - __fdividef(2.0f, e + 1.0f);
}
// grid barrier, cooperative-groups style: one gpu fence by t0, not 512 membars
__device__ __forceinline__ void grid_barrier() {
    __syncthreads();
    if (threadIdx.x == 0) {
        asm volatile("fence.acq_rel.gpu;" ::: "memory");   // release CTA's writes
        unsigned gen = g_bar_gen;
        if (atomicAdd(&g_bar_cnt, 1u) == (unsigned)(NBLK - 1)) {
            g_bar_cnt = 0u;
            asm volatile("fence.acq_rel.gpu;" ::: "memory"); // acquire others + order reset<gen
            g_bar_gen = gen + 1u;
        } else {
            while (g_bar_gen == gen) { __nanosleep(20); }
            asm volatile("fence.acq_rel.gpu;" ::: "memory"); // acquire
        }
    }
    __syncthreads();
}
__device__ __forceinline__ void ffma2(u64t& d, u64t a, u64t b) {
    asm volatile("fma.rn.f32x2 %0, %1, %2, %0;" : "+l"(d) : "l"(a), "l"(b));
}
__device__ __forceinline__ u64t dup2(float w) {
    u64t r;
    asm("mov.b64 %0, {%1, %1};" : "=l"(r) : "f"(w));
    return r;
}
__device__ __forceinline__ u64t pack2(float a, float b) {
    u64t r;
    asm("mov.b64 %0, {%1, %2};" : "=l"(r) : "f"(a), "f"(b));
    return r;
}
__device__ __forceinline__ float2 unpack2(u64t v) {
    float2 r;
    asm("mov.b64 {%0, %1}, %2;" : "=f"(r.x), "=f"(r.y) : "l"(v));
    return r;
}
__device__ __forceinline__ u64t addx2(u64t a, u64t b) {
    u64t r;
    asm("add.rn.f32x2 %0, %1, %2;" : "=l"(r) : "l"(a), "l"(b));
    return r;
}
__device__ __forceinline__ void cp16(void* dst, const float* src) {
    unsigned d = (unsigned)__cvta_generic_to_shared(dst);
    asm volatile("cp.async.cg.shared.global [%0], [%1], 16;" :: "r"(d), "l"(src));
}

// ---------------------------------------------------------------------------
// Precompute: pre0[t][g][b] = b_ih0[g]+b_hh0[g] + sum_k x[t][b][k]*W_ih0[g][k]
// Tile 128g x 128b per block, 256 threads, thread = 8g x 8b (4 pairs).
// Per kk: 4 LDS.128 + 8 dup movs + 32 FFMA2 -> FFMA2-pipe bound.
// grid = (8 gt, 512 t)
// ---------------------------------------------------------------------------
__global__ __launch_bounds__(256, 2) void precompute_kernel(
    const float* __restrict__ x, const float* __restrict__ W_ih,
    const float* __restrict__ b_ih, const float* __restrict__ b_hh)
{
    __shared__ __align__(16) u64t  Xs[32][66];    // [k][bpair 0..63] (+2 pad)
    __shared__ __align__(16) float Ws[32][132];   // [k][g 0..127]   (+4 pad)
    const int gt = blockIdx.x;
    const int t  = blockIdx.y;
    const int tid = threadIdx.x;
    const int gy = tid >> 4;      // 0..15 -> 8 g each
    const int bx = tid & 15;      // 0..15 -> pairs bx*4..+3 (b = 8bx..8bx+7)

    const float* xb = x + (size_t)t * Bn * Hn;
    const float* wb = W_ih + (size_t)(gt * 128) * Hn;

    u64t acc[8][4];
#pragma unroll
    for (int i = 0; i < 8; i++)
#pragma unroll
        for (int j = 0; j < 4; j++) acc[i][j] = 0ull;

    for (int kc = 0; kc < Hn; kc += 32) {
        {   // Xs fill: thread -> pair bp, 8 k values
            int bp = tid & 63;
            int kq = (tid >> 6) * 8;
            const float* r0 = xb + (size_t)(2 * bp) * Hn + kc + kq;
            const float* r1 = r0 + Hn;
            float4 a0 = *reinterpret_cast<const float4*>(r0);
            float4 a1 = *reinterpret_cast<const float4*>(r0 + 4);
            float4 b0 = *reinterpret_cast<const float4*>(r1);
            float4 b1 = *reinterpret_cast<const float4*>(r1 + 4);
            Xs[kq + 0][bp] = pack2(a0.x, b0.x);
            Xs[kq + 1][bp] = pack2(a0.y, b0.y);
            Xs[kq + 2][bp] = pack2(a0.z, b0.z);
            Xs[kq + 3][bp] = pack2(a0.w, b0.w);
            Xs[kq + 4][bp] = pack2(a1.x, b1.x);
            Xs[kq + 5][bp] = pack2(a1.y, b1.y);
            Xs[kq + 6][bp] = pack2(a1.z, b1.z);
            Xs[kq + 7][bp] = pack2(a1.w, b1.w);
        }
        {   // Ws fill: thread -> g, 16 k values (plain floats)
            int g   = tid & 127;
            int kq2 = (tid >> 7) * 16;
            const float* wr = wb + (size_t)g * Hn + kc + kq2;
            float4 w0 = *reinterpret_cast<const float4*>(wr);
            float4 w1 = *reinterpret_cast<const float4*>(wr + 4);
            float4 w2 = *reinterpret_cast<const float4*>(wr + 8);
            float4 w3 = *reinterpret_cast<const float4*>(wr + 12);
            Ws[kq2 +  0][g] = w0.x; Ws[kq2 +  1][g] = w0.y;
            Ws[kq2 +  2][g] = w0.z; Ws[kq2 +  3][g] = w0.w;
            Ws[kq2 +  4][g] = w1.x; Ws[kq2 +  5][g] = w1.y;
            Ws[kq2 +  6][g] = w1.z; Ws[kq2 +  7][g] = w1.w;
            Ws[kq2 +  8][g] = w2.x; Ws[kq2 +  9][g] = w2.y;
            Ws[kq2 + 10][g] = w2.z; Ws[kq2 + 11][g] = w2.w;
            Ws[kq2 + 12][g] = w3.x; Ws[kq2 + 13][g] = w3.y;
            Ws[kq2 + 14][g] = w3.z; Ws[kq2 + 15][g] = w3.w;
        }
        __syncthreads();
#pragma unroll
        for (int kk = 0; kk < 32; kk++) {
            ulonglong2 h01 = *reinterpret_cast<const ulonglong2*>(&Xs[kk][bx * 4]);
            ulonglong2 h23 = *reinterpret_cast<const ulonglong2*>(&Xs[kk][bx * 4 + 2]);
            float4 wa = *reinterpret_cast<const float4*>(&Ws[kk][gy * 8]);
            float4 wbv = *reinterpret_cast<const float4*>(&Ws[kk][gy * 8 + 4]);
            u64t wd[8] = { dup2(wa.x), dup2(wa.y), dup2(wa.z), dup2(wa.w),
                           dup2(wbv.x), dup2(wbv.y), dup2(wbv.z), dup2(wbv.w) };
            u64t hh[4] = { h01.x, h01.y, h23.x, h23.y };
#pragma unroll
            for (int gi = 0; gi < 8; gi++)
#pragma unroll
                for (int j = 0; j < 4; j++)
                    ffma2(acc[gi][j], hh[j], wd[gi]);
        }
        __syncthreads();
    }
#pragma unroll
    for (int gi = 0; gi < 8; gi++) {
        int g = gt * 128 + gy * 8 + gi;
        float bias = __ldg(b_ih + g) + __ldg(b_hh + g);
        float2 u0 = unpack2(acc[gi][0]);
        float2 u1 = unpack2(acc[gi][1]);
        float2 u2 = unpack2(acc[gi][2]);
        float2 u3 = unpack2(acc[gi][3]);
        float* op = g_pre0 + (size_t)t * (Gn * Bn) + (size_t)g * Bn + bx * 8;
        *reinterpret_cast<float4*>(op) =
            make_float4(u0.x + bias, u0.y + bias, u1.x + bias, u1.y + bias);
        *reinterpret_cast<float4*>(op + 4) =
            make_float4(u2.x + bias, u2.y + bias, u3.x + bias, u3.y + bias);
    }
}

// ---------------------------------------------------------------------------
// Persistent skewed recurrence. 128 CTAs x 512 threads. (R8 structure)
// CTA: bh = blk&1 (batch half), cg = blk>>1 (4 h-cols of both layers).
// Warps: bsel = w&3 (16-batch slice), kshi = w>>2 (64-K slice).
// Lanes: cs = lane&7 (2 col-pairs), kslo = lane>>3 (16-K sub-slice).
// ---------------------------------------------------------------------------
#define SM_WA    0
#define SM_WB    32768
#define SM_STAGE 49152
#define SM_PART  182272
#define SMEM_TOTAL 220160

__global__ __launch_bounds__(512, 1) void lstm_persistent(
    const float* __restrict__ W_ih, const float* __restrict__ W_hh,
    const float* __restrict__ b_ih, const float* __restrict__ b_hh,
    float* __restrict__ out)
{
    extern __shared__ __align__(16) char smraw[];
    char* smWA   = smraw + SM_WA;
    char* smWB   = smraw + SM_WB;
    char* stage  = smraw + SM_STAGE;
    char* partc  = smraw + SM_PART;

    const int tid  = threadIdx.x;
    const int blk  = blockIdx.x;
    const int bh   = blk & 1;
    const int cg   = blk >> 1;
    const int w    = tid >> 5;
    const int lane = tid & 31;
    const int bsel = w & 3;
    const int kshi = w >> 2;
    const int cs   = lane & 7;
    const int kslo = lane >> 3;

    // ---- weights into smem (plain floats, once) ----
    {
        int p  = tid & 15;
        int kg = tid >> 4;
        int gc = (p >> 2) * Hn + cg * 4 + (p & 3);
        const float* wh0 = W_hh + (size_t)gc * Hn;
        const float* wi1 = W_ih + (size_t)Gn * Hn + (size_t)gc * Hn;
        float* WA = reinterpret_cast<float*>(smWA);
#pragma unroll
        for (int j = 0; j < 8; j++) {
            int k = kg * 8 + j;
            WA[k * 32 + p * 2 + 0] = __ldg(wh0 + k);
            WA[k * 32 + p * 2 + 1] = __ldg(wi1 + k);
        }
        int c   = tid & 7;
        int kg2 = tid >> 3;
        int gcA = ((2 * c) >> 2) * Hn + cg * 4 + ((2 * c) & 3);
        int gcB = ((2 * c + 1) >> 2) * Hn + cg * 4 + ((2 * c + 1) & 3);
        const float* wh1a = W_hh + (size_t)Gn * Hn + (size_t)gcA * Hn;
        const float* wh1b = W_hh + (size_t)Gn * Hn + (size_t)gcB * Hn;
        float* WB = reinterpret_cast<float*>(smWB);
#pragma unroll
        for (int j = 0; j < 4; j++) {
            int k = kg2 * 4 + j;
            WB[k * 16 + c * 2 + 0] = __ldg(wh1a + k);
            WB[k * 16 + c * 2 + 1] = __ldg(wh1b + k);
        }
    }
    const int hcl = (tid >> 6) & 3;
    const int bl  = tid & 63;
    const int hcol = cg * 4 + hcl;
    const int b = bh * 64 + bl;
    float b1s[4];
#pragma unroll
    for (int g = 0; g < 4; g++)
        b1s[g] = __ldg(b_ih + Gn + g * Hn + hcol) + __ldg(b_hh + Gn + g * Hn + hcol);

    char* myStA = stage + w * 8320;
    char* myStB = myStA + 4160;

    {
        int idx = blk * 512 + tid;
        reinterpret_cast<float*>(g_h0)[idx] = 0.f;
        reinterpret_cast<float*>(g_h1)[idx] = 0.f;
    }
    float creg = 0.f;

    const size_t OUT_H = (size_t)Tn * Bn * Hn;
    const size_t OUT_C = OUT_H + 2 * (size_t)Bn * Hn;

    grid_barrier();

    for (int i = 0; i <= Tn; i++) {
        const int rslot = (i & 1) ^ 1;
        const int wslot = i & 1;
        const float* hA = g_h0[rslot];
        const float* hB = g_h1[rslot];

        // ===== warp-private staging (A then B), kslo-padded =====
#pragma unroll
        for (int j = 0; j < 8; j++) {
            int f = lane + j * 32;
            int ksb = f >> 6, rem = f & 63;
            int krow = rem >> 2, seg = rem & 3;
            int k = kshi * 64 + ksb * 16 + krow;
            size_t so = (size_t)k * Bn + bh * 64 + bsel * 16 + seg * 4;
            cp16(myStA + ksb * 1040 + krow * 64 + seg * 16, hA + so);
        }
        asm volatile("cp.async.commit_group;");
#pragma unroll
        for (int j = 0; j < 8; j++) {
            int f = lane + j * 32;
            int ksb = f >> 6, rem = f & 63;
            int krow = rem >> 2, seg = rem & 3;
            int k = kshi * 64 + ksb * 16 + krow;
            size_t so = (size_t)k * Bn + bh * 64 + bsel * 16 + seg * 4;
            cp16(myStB + ksb * 1040 + krow * 64 + seg * 16, hB + so);
        }
        asm volatile("cp.async.commit_group;");

        float pg[4] = {0.f, 0.f, 0.f, 0.f};
        if (tid < 256 && i < Tn) {
            const float* pb = g_pre0 + (size_t)i * (Gn * Bn);
#pragma unroll
            for (int g = 0; g < 4; g++)
                pg[g] = __ldg(pb + (size_t)(g * Hn + hcol) * Bn + b);
        }

        u64t acc[4][8];
#pragma unroll
        for (int r = 0; r < 4; r++)
#pragma unroll
            for (int j = 0; j < 8; j++) acc[r][j] = 0ull;

        asm volatile("cp.async.wait_group 1;");
        __syncwarp();
        // ===== phase A: L0-rec + L1-input on h0 slice (fully unrolled) =====
        {
            const char* hp = myStA + kslo * 1040;
            const char* wp = smWA + (size_t)(kshi * 64 + kslo * 16) * 128 + cs * 16;
#pragma unroll
            for (int u = 0; u < 16; u++) {
                ulonglong2 h0v = *reinterpret_cast<const ulonglong2*>(hp);
                ulonglong2 h1v = *reinterpret_cast<const ulonglong2*>(hp + 16);
                ulonglong2 h2v = *reinterpret_cast<const ulonglong2*>(hp + 32);
                ulonglong2 h3v = *reinterpret_cast<const ulonglong2*>(hp + 48);
                float4 wv = *reinterpret_cast<const float4*>(wp);
                u64t w0a = dup2(wv.x), w1a = dup2(wv.y);
                u64t w0b = dup2(wv.z), w1b = dup2(wv.w);
                u64t hh[8] = {h0v.x, h0v.y, h1v.x, h1v.y, h2v.x, h2v.y, h3v.x, h3v.y};
#pragma unroll
                for (int j = 0; j < 8; j++) {
                    ffma2(acc[0][j], hh[j], w0a);
                    ffma2(acc[2][j], hh[j], w1a);
                    ffma2(acc[1][j], hh[j], w0b);
                    ffma2(acc[3][j], hh[j], w1b);
                }
                hp += 64; wp += 128;
            }
        }
        asm volatile("cp.async.wait_group 0;");
        __syncwarp();
        // ===== phase B: L1-rec on h1 slice (fully unrolled) =====
        {
            const char* hp = myStB + kslo * 1040;
            const char* wp = smWB + (size_t)(kshi * 64 + kslo * 16) * 64 + cs * 8;
#pragma unroll
            for (int u = 0; u < 16; u++) {
                ulonglong2 h0v = *reinterpret_cast<const ulonglong2*>(hp);
                ulonglong2 h1v = *reinterpret_cast<const ulonglong2*>(hp + 16);
                ulonglong2 h2v = *reinterpret_cast<const ulonglong2*>(hp + 32);
                ulonglong2 h3v = *reinterpret_cast<const ulonglong2*>(hp + 48);
                float2 wv = *reinterpret_cast<const float2*>(wp);
                u64t w2a = dup2(wv.x), w2b = dup2(wv.y);
                u64t hh[8] = {h0v.x, h0v.y, h1v.x, h1v.y, h2v.x, h2v.y, h3v.x, h3v.y};
#pragma unroll
                for (int j = 0; j < 8; j++) {
                    ffma2(acc[2][j], hh[j], w2a);
                    ffma2(acc[3][j], hh[j], w2b);
                }
                hp += 64; wp += 64;
            }
        }

        // ===== in-warp reduce over kslo (xor 8, xor 16) =====
#pragma unroll
        for (int r = 0; r < 4; r++)
#pragma unroll
            for (int j = 0; j < 8; j++) {
                u64t v = acc[r][j];
                v = addx2(v, (u64t)__shfl_xor_sync(0xFFFFFFFFu, v, 8));
                v = addx2(v, (u64t)__shfl_xor_sync(0xFFFFFFFFu, v, 16));
                acc[r][j] = v;
            }
        if (kslo == 0) {
#pragma unroll
            for (int r = 0; r < 4; r++) {
                int row = (r < 2) ? (2 * cs + r) : (16 + 2 * cs + (r - 2));
                char* pb = partc + row * 1184 + kshi * 288 + bsel * 64;
                reinterpret_cast<ulonglong2*>(pb)[0] = make_ulonglong2(acc[r][0], acc[r][1]);
                reinterpret_cast<ulonglong2*>(pb)[1] = make_ulonglong2(acc[r][2], acc[r][3]);
                reinterpret_cast<ulonglong2*>(pb)[2] = make_ulonglong2(acc[r][4], acc[r][5]);
                reinterpret_cast<ulonglong2*>(pb)[3] = make_ulonglong2(acc[r][6], acc[r][7]);
            }
        }
        __syncthreads();

        // ===== elementwise =====
        if (tid < 256) {
            if (i < Tn) {
                float s[4];
#pragma unroll
                for (int g = 0; g < 4; g++) {
                    const float* pr = reinterpret_cast<const float*>(
                        partc + (g * 4 + hcl) * 1184 + bl * 4);
                    s[g] = pg[g] + pr[0] + pr[72] + pr[144] + pr[216];
                }
                float cn = fsig(s[1]) * creg + fsig(s[0]) * ftanh2(s[2]);
                creg = cn;
                float hn = fsig(s[3]) * ftanh2(cn);
                __stcg(&g_h0[wslot][hcol * Bn + b], hn);
                if (i == Tn - 1) {
                    out[OUT_H + (size_t)b * Hn + hcol] = hn;
                    out[OUT_C + (size_t)b * Hn + hcol] = cn;
                }
            }
        } else {
            if (i >= 1) {
                const int t1 = i - 1;
                float s[4];
#pragma unroll
                for (int g = 0; g < 4; g++) {
                    const float* pr = reinterpret_cast<const float*>(
                        partc + (16 + g * 4 + hcl) * 1184 + bl * 4);
                    s[g] = b1s[g] + pr[0] + pr[72] + pr[144] + pr[216];
                }
                float cn = fsig(s[1]) * creg + fsig(s[0]) * ftanh2(s[2]);
                creg = cn;
                float hn = fsig(s[3]) * ftanh2(cn);
                __stcg(&g_h1[wslot][hcol * Bn + b], hn);
                out[(size_t)t1 * (Bn * Hn) + (size_t)b * Hn + hcol] = hn;
                if (i == Tn) {
                    out[OUT_H + (size_t)Bn * Hn + (size_t)b * Hn + hcol] = hn;
                    out[OUT_C + (size_t)Bn * Hn + (size_t)b * Hn + hcol] = cn;
                }
            }
        }
        grid_barrier();
    }
}

extern "C" void kernel_launch(void* const* d_in, const int* in_sizes, int n_in,
                              void* d_out, int out_size) {
    (void)in_sizes; (void)n_in; (void)out_size;
    const float* x    = (const float*)d_in[0];
    const float* W_ih = (const float*)d_in[1];
    const float* W_hh = (const float*)d_in[2];
    const float* b_ih = (const float*)d_in[3];
    const float* b_hh = (const float*)d_in[4];
    float* out = (float*)d_out;

    cudaFuncSetAttribute(lstm_persistent,
                         cudaFuncAttributeMaxDynamicSharedMemorySize, SMEM_TOTAL);

    dim3 gPre(8, 512);
    precompute_kernel<<<gPre, 256>>>(x, W_ih, b_ih, b_hh);
    lstm_persistent<<<NBLK, 512, SMEM_TOTAL>>>(W_ih, W_hh, b_ih, b_hh, out);
}

// round 10
// speedup vs baseline: 3.7097x; 1.0552x over previous
#include <cuda_runtime.h>
#include <cstdint>

#define Tn 512
#define Bn 128
#define Hn 256
#define Gn 1024
#define NBLK 256

typedef unsigned long long u64t;

// ---------------- device scratch ----------------
__device__ float g_pre0[(size_t)Tn * Gn * Bn];   // [t][gatecol][b]
__device__ float g_h0[2][Hn * Bn];               // [pp][h][b]
__device__ float g_h1[2][Hn * Bn];
__device__ volatile unsigned g_bar_gen = 0;
__device__ unsigned g_bar_cnt = 0;

__device__ __forceinline__ float fsig(float x) {
    return __fdividef(1.0f, 1.0f + __expf(-x));
}
__device__ __forceinline__ float ftanh2(float x) {
    float e = __expf(2.0f * x);
    return 1.0f - __fdividef(2.0f, e + 1.0f);
}
// grid barrier: one gpu fence by t0 per CTA
__device__ __forceinline__ void grid_barrier() {
    __syncthreads();
    if (threadIdx.x == 0) {
        asm volatile("fence.acq_rel.gpu;" ::: "memory");
        unsigned gen = g_bar_gen;
        if (atomicAdd(&g_bar_cnt, 1u) == (unsigned)(NBLK - 1)) {
            g_bar_cnt = 0u;
            asm volatile("fence.acq_rel.gpu;" ::: "memory");
            g_bar_gen = gen + 1u;
        } else {
            while (g_bar_gen == gen) { __nanosleep(20); }
            asm volatile("fence.acq_rel.gpu;" ::: "memory");
        }
    }
    __syncthreads();
}
__device__ __forceinline__ void ffma2(u64t& d, u64t a, u64t b) {
    asm volatile("fma.rn.f32x2 %0, %1, %2, %0;" : "+l"(d) : "l"(a), "l"(b));
}
__device__ __forceinline__ u64t dup2(float w) {
    u64t r;
    asm("mov.b64 %0, {%1, %1};" : "=l"(r) : "f"(w));
    return r;
}
__device__ __forceinline__ u64t pack2(float a, float b) {
    u64t r;
    asm("mov.b64 %0, {%1, %2};" : "=l"(r) : "f"(a), "f"(b));
    return r;
}
__device__ __forceinline__ float2 unpack2(u64t v) {
    float2 r;
    asm("mov.b64 {%0, %1}, %2;" : "=f"(r.x), "=f"(r.y) : "l"(v));
    return r;
}
__device__ __forceinline__ u64t addx2(u64t a, u64t b) {
    u64t r;
    asm("add.rn.f32x2 %0, %1, %2;" : "=l"(r) : "l"(a), "l"(b));
    return r;
}
__device__ __forceinline__ void cp16(void* dst, const float* src) {
    unsigned d = (unsigned)__cvta_generic_to_shared(dst);
    asm volatile("cp.async.cg.shared.global [%0], [%1], 16;" :: "r"(d), "l"(src));
}

// ---------------------------------------------------------------------------
// Precompute (unchanged from R9): pre0[t][g][b]
// Tile 128g x 128b per block, 256 threads, thread = 8g x 8b. grid (8, 512).
// ---------------------------------------------------------------------------
__global__ __launch_bounds__(256, 2) void precompute_kernel(
    const float* __restrict__ x, const float* __restrict__ W_ih,
    const float* __restrict__ b_ih, const float* __restrict__ b_hh)
{
    __shared__ __align__(16) u64t  Xs[32][66];
    __shared__ __align__(16) float Ws[32][132];
    const int gt = blockIdx.x;
    const int t  = blockIdx.y;
    const int tid = threadIdx.x;
    const int gy = tid >> 4;
    const int bx = tid & 15;

    const float* xb = x + (size_t)t * Bn * Hn;
    const float* wb = W_ih + (size_t)(gt * 128) * Hn;

    u64t acc[8][4];
#pragma unroll
    for (int i = 0; i < 8; i++)
#pragma unroll
        for (int j = 0; j < 4; j++) acc[i][j] = 0ull;

    for (int kc = 0; kc < Hn; kc += 32) {
        {
            int bp = tid & 63;
            int kq = (tid >> 6) * 8;
            const float* r0 = xb + (size_t)(2 * bp) * Hn + kc + kq;
            const float* r1 = r0 + Hn;
            float4 a0 = *reinterpret_cast<const float4*>(r0);
            float4 a1 = *reinterpret_cast<const float4*>(r0 + 4);
            float4 b0 = *reinterpret_cast<const float4*>(r1);
            float4 b1 = *reinterpret_cast<const float4*>(r1 + 4);
            Xs[kq + 0][bp] = pack2(a0.x, b0.x);
            Xs[kq + 1][bp] = pack2(a0.y, b0.y);
            Xs[kq + 2][bp] = pack2(a0.z, b0.z);
            Xs[kq + 3][bp] = pack2(a0.w, b0.w);
            Xs[kq + 4][bp] = pack2(a1.x, b1.x);
            Xs[kq + 5][bp] = pack2(a1.y, b1.y);
            Xs[kq + 6][bp] = pack2(a1.z, b1.z);
            Xs[kq + 7][bp] = pack2(a1.w, b1.w);
        }
        {
            int g   = tid & 127;
            int kq2 = (tid >> 7) * 16;
            const float* wr = wb + (size_t)g * Hn + kc + kq2;
            float4 w0 = *reinterpret_cast<const float4*>(wr);
            float4 w1 = *reinterpret_cast<const float4*>(wr + 4);
            float4 w2 = *reinterpret_cast<const float4*>(wr + 8);
            float4 w3 = *reinterpret_cast<const float4*>(wr + 12);
            Ws[kq2 +  0][g] = w0.x; Ws[kq2 +  1][g] = w0.y;
            Ws[kq2 +  2][g] = w0.z; Ws[kq2 +  3][g] = w0.w;
            Ws[kq2 +  4][g] = w1.x; Ws[kq2 +  5][g] = w1.y;
            Ws[kq2 +  6][g] = w1.z; Ws[kq2 +  7][g] = w1.w;
            Ws[kq2 +  8][g] = w2.x; Ws[kq2 +  9][g] = w2.y;
            Ws[kq2 + 10][g] = w2.z; Ws[kq2 + 11][g] = w2.w;
            Ws[kq2 + 12][g] = w3.x; Ws[kq2 + 13][g] = w3.y;
            Ws[kq2 + 14][g] = w3.z; Ws[kq2 + 15][g] = w3.w;
        }
        __syncthreads();
#pragma unroll
        for (int kk = 0; kk < 32; kk++) {
            ulonglong2 h01 = *reinterpret_cast<const ulonglong2*>(&Xs[kk][bx * 4]);
            ulonglong2 h23 = *reinterpret_cast<const ulonglong2*>(&Xs[kk][bx * 4 + 2]);
            float4 wa = *reinterpret_cast<const float4*>(&Ws[kk][gy * 8]);
            float4 wbv = *reinterpret_cast<const float4*>(&Ws[kk][gy * 8 + 4]);
            u64t wd[8] = { dup2(wa.x), dup2(wa.y), dup2(wa.z), dup2(wa.w),
                           dup2(wbv.x), dup2(wbv.y), dup2(wbv.z), dup2(wbv.w) };
            u64t hh[4] = { h01.x, h01.y, h23.x, h23.y };
#pragma unroll
            for (int gi = 0; gi < 8; gi++)
#pragma unroll
                for (int j = 0; j < 4; j++)
                    ffma2(acc[gi][j], hh[j], wd[gi]);
        }
        __syncthreads();
    }
#pragma unroll
    for (int gi = 0; gi < 8; gi++) {
        int g = gt * 128 + gy * 8 + gi;
        float bias = __ldg(b_ih + g) + __ldg(b_hh + g);
        float2 u0 = unpack2(acc[gi][0]);
        float2 u1 = unpack2(acc[gi][1]);
        float2 u2 = unpack2(acc[gi][2]);
        float2 u3 = unpack2(acc[gi][3]);
        float* op = g_pre0 + (size_t)t * (Gn * Bn) + (size_t)g * Bn + bx * 8;
        *reinterpret_cast<float4*>(op) =
            make_float4(u0.x + bias, u0.y + bias, u1.x + bias, u1.y + bias);
        *reinterpret_cast<float4*>(op + 4) =
            make_float4(u2.x + bias, u2.y + bias, u3.x + bias, u3.y + bias);
    }
}

// ---------------------------------------------------------------------------
// Persistent skewed recurrence. 256 CTAs x 256 threads (2 CTAs/SM).
// CTA: bq = blk&3 (batch quarter, 32), cg = blk>>2 (4 h-cols, both layers).
// Warps (8): bsel = w&1 (16-batch), kshi = w>>1 (64-K slice).
// Lanes: cs = lane&7 (2 col-pairs), kslo = lane>>3 (16-K sub-slice).
// Single staging buffer reused A->B; co-resident CTA hides the serial RT.
// smem: WA 32768 | WB 16384 | stage 8x4160=33280 | part 32x528=16896 -> 99328
// ---------------------------------------------------------------------------
#define SM_WA    0
#define SM_WB    32768
#define SM_STAGE 49152
#define SM_PART  82432
#define SMEM_TOTAL 99328

__global__ __launch_bounds__(256, 2) void lstm_persistent(
    const float* __restrict__ W_ih, const float* __restrict__ W_hh,
    const float* __restrict__ b_ih, const float* __restrict__ b_hh,
    float* __restrict__ out)
{
    extern __shared__ __align__(16) char smraw[];
    char* smWA   = smraw + SM_WA;
    char* smWB   = smraw + SM_WB;
    char* stage  = smraw + SM_STAGE;
    char* partc  = smraw + SM_PART;

    const int tid  = threadIdx.x;
    const int blk  = blockIdx.x;
    const int bq   = blk & 3;
    const int cg   = blk >> 2;
    const int w    = tid >> 5;
    const int lane = tid & 31;
    const int bsel = w & 1;
    const int kshi = w >> 1;          // 0..3
    const int cs   = lane & 7;
    const int kslo = lane >> 3;       // 0..3

    // ---- weights into smem (plain floats, once) ----
    {
        int p  = tid & 15;
        int kg = tid >> 4;            // 0..15 -> 16 k each
        int gc = (p >> 2) * Hn + cg * 4 + (p & 3);
        const float* wh0 = W_hh + (size_t)gc * Hn;
        const float* wi1 = W_ih + (size_t)Gn * Hn + (size_t)gc * Hn;
        float* WA = reinterpret_cast<float*>(smWA);
#pragma unroll
        for (int j = 0; j < 16; j++) {
            int k = kg * 16 + j;
            WA[k * 32 + p * 2 + 0] = __ldg(wh0 + k);
            WA[k * 32 + p * 2 + 1] = __ldg(wi1 + k);
        }
        int c   = tid & 7;
        int kg2 = tid >> 3;           // 0..31 -> 8 k each
        int gcA = ((2 * c) >> 2) * Hn + cg * 4 + ((2 * c) & 3);
        int gcB = ((2 * c + 1) >> 2) * Hn + cg * 4 + ((2 * c + 1) & 3);
        const float* wh1a = W_hh + (size_t)Gn * Hn + (size_t)gcA * Hn;
        const float* wh1b = W_hh + (size_t)Gn * Hn + (size_t)gcB * Hn;
        float* WB = reinterpret_cast<float*>(smWB);
#pragma unroll
        for (int j = 0; j < 8; j++) {
            int k = kg2 * 8 + j;
            WB[k * 16 + c * 2 + 0] = __ldg(wh1a + k);
            WB[k * 16 + c * 2 + 1] = __ldg(wh1b + k);
        }
    }
    // elementwise identity (EW0: tid<128, EW1: tid>=128)
    const int hcl = (tid >> 5) & 3;
    const int bl  = tid & 31;
    const int hcol = cg * 4 + hcl;
    const int b = bq * 32 + bl;
    float b1s[4];
#pragma unroll
    for (int g = 0; g < 4; g++)
        b1s[g] = __ldg(b_ih + Gn + g * Hn + hcol) + __ldg(b_hh + Gn + g * Hn + hcol);

    // per-warp staging pointer (single buffer, 4 kslo-blocks of 1040B)
    char* myst = stage + w * 4160;

    // zero init h ping-pong buffers (256 CTAs x 256 threads = 65536)
    {
        int idx = blk * 256 + tid;
        reinterpret_cast<float*>(g_h0)[idx] = 0.f;
        reinterpret_cast<float*>(g_h1)[idx] = 0.f;
    }
    float creg = 0.f;

    const size_t OUT_H = (size_t)Tn * Bn * Hn;
    const size_t OUT_C = OUT_H + 2 * (size_t)Bn * Hn;

    grid_barrier();   // init + weights visible

    for (int i = 0; i <= Tn; i++) {
        const int rslot = (i & 1) ^ 1;
        const int wslot = i & 1;
        const float* hA = g_h0[rslot];
        const float* hB = g_h1[rslot];

        // ===== stage A (h0 slice) =====
#pragma unroll
        for (int j = 0; j < 8; j++) {
            int f = lane + j * 32;
            int ksb = f >> 6, rem = f & 63;
            int krow = rem >> 2, seg = rem & 3;
            int k = kshi * 64 + ksb * 16 + krow;
            size_t so = (size_t)k * Bn + bq * 32 + bsel * 16 + seg * 4;
            cp16(myst + ksb * 1040 + krow * 64 + seg * 16, hA + so);
        }
        asm volatile("cp.async.commit_group;");

        // prefetch pre0 gates (EW0 operand) while staging flies
        float pg[4] = {0.f, 0.f, 0.f, 0.f};
        if (tid < 128 && i < Tn) {
            const float* pb = g_pre0 + (size_t)i * (Gn * Bn);
#pragma unroll
            for (int g = 0; g < 4; g++)
                pg[g] = __ldg(pb + (size_t)(g * Hn + hcol) * Bn + b);
        }

        u64t acc[4][8];
#pragma unroll
        for (int r = 0; r < 4; r++)
#pragma unroll
            for (int j = 0; j < 8; j++) acc[r][j] = 0ull;

        asm volatile("cp.async.wait_group 0;");
        __syncwarp();
        // ===== phase A: L0-rec + L1-input on h0 slice =====
        {
            const char* hp = myst + kslo * 1040;
            const char* wp = smWA + (size_t)(kshi * 64 + kslo * 16) * 128 + cs * 16;
#pragma unroll
            for (int u = 0; u < 16; u++) {
                ulonglong2 h0v = *reinterpret_cast<const ulonglong2*>(hp);
                ulonglong2 h1v = *reinterpret_cast<const ulonglong2*>(hp + 16);
                ulonglong2 h2v = *reinterpret_cast<const ulonglong2*>(hp + 32);
                ulonglong2 h3v = *reinterpret_cast<const ulonglong2*>(hp + 48);
                float4 wv = *reinterpret_cast<const float4*>(wp);
                u64t w0a = dup2(wv.x), w1a = dup2(wv.y);
                u64t w0b = dup2(wv.z), w1b = dup2(wv.w);
                u64t hh[8] = {h0v.x, h0v.y, h1v.x, h1v.y, h2v.x, h2v.y, h3v.x, h3v.y};
#pragma unroll
                for (int j = 0; j < 8; j++) {
                    ffma2(acc[0][j], hh[j], w0a);
                    ffma2(acc[2][j], hh[j], w1a);
                    ffma2(acc[1][j], hh[j], w0b);
                    ffma2(acc[3][j], hh[j], w1b);
                }
                hp += 64; wp += 128;
            }
        }
        __syncwarp();
        // ===== stage B (h1 slice) into the same buffer =====
#pragma unroll
        for (int j = 0; j < 8; j++) {
            int f = lane + j * 32;
            int ksb = f >> 6, rem = f & 63;
            int krow = rem >> 2, seg = rem & 3;
            int k = kshi * 64 + ksb * 16 + krow;
            size_t so = (size_t)k * Bn + bq * 32 + bsel * 16 + seg * 4;
            cp16(myst + ksb * 1040 + krow * 64 + seg * 16, hB + so);
        }
        asm volatile("cp.async.commit_group;");
        asm volatile("cp.async.wait_group 0;");
        __syncwarp();
        // ===== phase B: L1-rec on h1 slice (accumulate into L1 accs) =====
        {
            const char* hp = myst + kslo * 1040;
            const char* wp = smWB + (size_t)(kshi * 64 + kslo * 16) * 64 + cs * 8;
#pragma unroll
            for (int u = 0; u < 16; u++) {
                ulonglong2 h0v = *reinterpret_cast<const ulonglong2*>(hp);
                ulonglong2 h1v = *reinterpret_cast<const ulonglong2*>(hp + 16);
                ulonglong2 h2v = *reinterpret_cast<const ulonglong2*>(hp + 32);
                ulonglong2 h3v = *reinterpret_cast<const ulonglong2*>(hp + 48);
                float2 wv = *reinterpret_cast<const float2*>(wp);
                u64t w2a = dup2(wv.x), w2b = dup2(wv.y);
                u64t hh[8] = {h0v.x, h0v.y, h1v.x, h1v.y, h2v.x, h2v.y, h3v.x, h3v.y};
#pragma unroll
                for (int j = 0; j < 8; j++) {
                    ffma2(acc[2][j], hh[j], w2a);
                    ffma2(acc[3][j], hh[j], w2b);
                }
                hp += 64; wp += 64;
            }
        }

        // ===== in-warp reduce over kslo (xor 8, xor 16) =====
#pragma unroll
        for (int r = 0; r < 4; r++)
#pragma unroll
            for (int j = 0; j < 8; j++) {
                u64t v = acc[r][j];
                v = addx2(v, (u64t)__shfl_xor_sync(0xFFFFFFFFu, v, 8));
                v = addx2(v, (u64t)__shfl_xor_sync(0xFFFFFFFFu, v, 16));
                acc[r][j] = v;
            }
        if (kslo == 0) {
#pragma unroll
            for (int r = 0; r < 4; r++) {
                int row = (r < 2) ? (2 * cs + r) : (16 + 2 * cs + (r - 2));
                char* pb = partc + row * 528 + kshi * 128 + bsel * 64;
                reinterpret_cast<ulonglong2*>(pb)[0] = make_ulonglong2(acc[r][0], acc[r][1]);
                reinterpret_cast<ulonglong2*>(pb)[1] = make_ulonglong2(acc[r][2], acc[r][3]);
                reinterpret_cast<ulonglong2*>(pb)[2] = make_ulonglong2(acc[r][4], acc[r][5]);
                reinterpret_cast<ulonglong2*>(pb)[3] = make_ulonglong2(acc[r][6], acc[r][7]);
            }
        }
        __syncthreads();

        // ===== elementwise (sum 4 kshi partials; bsel selects batch bytes) =====
        if (tid < 128) {
            if (i < Tn) {
                float s[4];
#pragma unroll
                for (int g = 0; g < 4; g++) {
                    const float* pr = reinterpret_cast<const float*>(
                        partc + (g * 4 + hcl) * 528 + bl * 4);
                    s[g] = pg[g] + pr[0] + pr[32] + pr[64] + pr[96];
                }
                float cn = fsig(s[1]) * creg + fsig(s[0]) * ftanh2(s[2]);
                creg = cn;
                float hn = fsig(s[3]) * ftanh2(cn);
                __stcg(&g_h0[wslot][hcol * Bn + b], hn);
                if (i == Tn - 1) {
                    out[OUT_H + (size_t)b * Hn + hcol] = hn;
                    out[OUT_C + (size_t)b * Hn + hcol] = cn;
                }
            }
        } else {
            if (i >= 1) {
                const int t1 = i - 1;
                float s[4];
#pragma unroll
                for (int g = 0; g < 4; g++) {
                    const float* pr = reinterpret_cast<const float*>(
                        partc + (16 + g * 4 + hcl) * 528 + bl * 4);
                    s[g] = b1s[g] + pr[0] + pr[32] + pr[64] + pr[96];
                }
                float cn = fsig(s[1]) * creg + fsig(s[0]) * ftanh2(s[2]);
                creg = cn;
                float hn = fsig(s[3]) * ftanh2(cn);
                __stcg(&g_h1[wslot][hcol * Bn + b], hn);
                out[(size_t)t1 * (Bn * Hn) + (size_t)b * Hn + hcol] = hn;
                if (i == Tn) {
                    out[OUT_H + (size_t)Bn * Hn + (size_t)b * Hn + hcol] = hn;
                    out[OUT_C + (size_t)Bn * Hn + (size_t)b * Hn + hcol] = cn;
                }
            }
        }
        grid_barrier();
    }
}

extern "C" void kernel_launch(void* const* d_in, const int* in_sizes, int n_in,
                              void* d_out, int out_size) {
    (void)in_sizes; (void)n_in; (void)out_size;
    const float* x    = (const float*)d_in[0];
    const float* W_ih = (const float*)d_in[1];
    const float* W_hh = (const float*)d_in[2];
    const float* b_ih = (const float*)d_in[3];
    const float* b_hh = (const float*)d_in[4];
    float* out = (float*)d_out;

    cudaFuncSetAttribute(lstm_persistent,
                         cudaFuncAttributeMaxDynamicSharedMemorySize, SMEM_TOTAL);

    dim3 gPre(8, 512);
    precompute_kernel<<<gPre, 256>>>(x, W_ih, b_ih, b_hh);
    lstm_persistent<<<NBLK, 256, SMEM_TOTAL>>>(W_ih, W_hh, b_ih, b_hh, out);
}

// round 11
// speedup vs baseline: 3.8674x; 1.0425x over previous
#include <cuda_runtime.h>
#include <cstdint>

#define Tn 512
#define Bn 128
#define Hn 256
#define Gn 1024
#define NBLK 256

typedef unsigned long long u64t;

// ---------------- device scratch ----------------
__device__ float g_pre0[(size_t)Tn * Gn * Bn];   // [t][gatecol][b]
__device__ float g_h0[2][Hn * Bn];               // [pp][h][b]
__device__ float g_h1[2][Hn * Bn];
__device__ volatile unsigned g_bar_gen = 0;
__device__ unsigned g_bar_cnt = 0;

__device__ __forceinline__ float fsig(float x) {
    return __fdividef(1.0f, 1.0f + __expf(-x));
}
__device__ __forceinline__ float ftanh2(float x) {
    float e = __expf(2.0f * x);
    return 1.0f - __fdividef(2.0f, e + 1.0f);
}
// grid barrier: one gpu fence by t0 per CTA
__device__ __forceinline__ void grid_barrier() {
    __syncthreads();
    if (threadIdx.x == 0) {
        asm volatile("fence.acq_rel.gpu;" ::: "memory");
        unsigned gen = g_bar_gen;
        if (atomicAdd(&g_bar_cnt, 1u) == (unsigned)(NBLK - 1)) {
            g_bar_cnt = 0u;
            asm volatile("fence.acq_rel.gpu;" ::: "memory");
            g_bar_gen = gen + 1u;
        } else {
            while (g_bar_gen == gen) { __nanosleep(20); }
            asm volatile("fence.acq_rel.gpu;" ::: "memory");
        }
    }
    __syncthreads();
}
__device__ __forceinline__ void ffma2(u64t& d, u64t a, u64t b) {
    asm volatile("fma.rn.f32x2 %0, %1, %2, %0;" : "+l"(d) : "l"(a), "l"(b));
}
__device__ __forceinline__ u64t dup2(float w) {
    u64t r;
    asm("mov.b64 %0, {%1, %1};" : "=l"(r) : "f"(w));
    return r;
}
__device__ __forceinline__ u64t pack2(float a, float b) {
    u64t r;
    asm("mov.b64 %0, {%1, %2};" : "=l"(r) : "f"(a), "f"(b));
    return r;
}
__device__ __forceinline__ float2 unpack2(u64t v) {
    float2 r;
    asm("mov.b64 {%0, %1}, %2;" : "=f"(r.x), "=f"(r.y) : "l"(v));
    return r;
}
__device__ __forceinline__ u64t addx2(u64t a, u64t b) {
    u64t r;
    asm("add.rn.f32x2 %0, %1, %2;" : "=l"(r) : "l"(a), "l"(b));
    return r;
}
__device__ __forceinline__ void cp16(void* dst, const float* src) {
    unsigned d = (unsigned)__cvta_generic_to_shared(dst);
    asm volatile("cp.async.cg.shared.global [%0], [%1], 16;" :: "r"(d), "l"(src));
}

// ---------------------------------------------------------------------------
// Precompute: pre0[t][g][b] = b_ih0[g]+b_hh0[g] + sum_k x[t][b][k]*W_ih0[g][k]
// Tile 128g x 128b, 256 threads, thread = 8g x 8b. K-chunk 64 (4 chunks).
// Dynamic smem: Xs u64[64][66] @0 (33792) | Ws float[64][132] @33792 (33792)
// ---------------------------------------------------------------------------
#define PRE_SMEM 67584

__global__ __launch_bounds__(256, 2) void precompute_kernel(
    const float* __restrict__ x, const float* __restrict__ W_ih,
    const float* __restrict__ b_ih, const float* __restrict__ b_hh)
{
    extern __shared__ __align__(16) char psm[];
    u64t*  Xs = reinterpret_cast<u64t*>(psm);            // [kk][66]
    float* Ws = reinterpret_cast<float*>(psm + 33792);   // [kk][132]
    const int gt = blockIdx.x;
    const int t  = blockIdx.y;
    const int tid = threadIdx.x;
    const int gy = tid >> 4;
    const int bx = tid & 15;

    const float* xb = x + (size_t)t * Bn * Hn;
    const float* wb = W_ih + (size_t)(gt * 128) * Hn;

    u64t acc[8][4];
#pragma unroll
    for (int i = 0; i < 8; i++)
#pragma unroll
        for (int j = 0; j < 4; j++) acc[i][j] = 0ull;

    for (int kc = 0; kc < Hn; kc += 64) {
        {   // Xs fill: thread -> batch pair bp, 16 k values
            int bp = tid & 63;
            int kq = (tid >> 6) * 16;
            const float* r0 = xb + (size_t)(2 * bp) * Hn + kc + kq;
            const float* r1 = r0 + Hn;
#pragma unroll
            for (int q = 0; q < 4; q++) {
                float4 a = *reinterpret_cast<const float4*>(r0 + q * 4);
                float4 b4 = *reinterpret_cast<const float4*>(r1 + q * 4);
                Xs[(kq + q * 4 + 0) * 66 + bp] = pack2(a.x, b4.x);
                Xs[(kq + q * 4 + 1) * 66 + bp] = pack2(a.y, b4.y);
                Xs[(kq + q * 4 + 2) * 66 + bp] = pack2(a.z, b4.z);
                Xs[(kq + q * 4 + 3) * 66 + bp] = pack2(a.w, b4.w);
            }
        }
        {   // Ws fill: thread -> g, 32 k values (plain floats)
            int g   = tid & 127;
            int kq2 = (tid >> 7) * 32;
            const float* wr = wb + (size_t)g * Hn + kc + kq2;
#pragma unroll
            for (int q = 0; q < 8; q++) {
                float4 wv = *reinterpret_cast<const float4*>(wr + q * 4);
                Ws[(kq2 + q * 4 + 0) * 132 + g] = wv.x;
                Ws[(kq2 + q * 4 + 1) * 132 + g] = wv.y;
                Ws[(kq2 + q * 4 + 2) * 132 + g] = wv.z;
                Ws[(kq2 + q * 4 + 3) * 132 + g] = wv.w;
            }
        }
        __syncthreads();
#pragma unroll
        for (int kk = 0; kk < 64; kk++) {
            ulonglong2 h01 = *reinterpret_cast<const ulonglong2*>(&Xs[kk * 66 + bx * 4]);
            ulonglong2 h23 = *reinterpret_cast<const ulonglong2*>(&Xs[kk * 66 + bx * 4 + 2]);
            float4 wa = *reinterpret_cast<const float4*>(&Ws[kk * 132 + gy * 8]);
            float4 wbv = *reinterpret_cast<const float4*>(&Ws[kk * 132 + gy * 8 + 4]);
            u64t wd[8] = { dup2(wa.x), dup2(wa.y), dup2(wa.z), dup2(wa.w),
                           dup2(wbv.x), dup2(wbv.y), dup2(wbv.z), dup2(wbv.w) };
            u64t hh[4] = { h01.x, h01.y, h23.x, h23.y };
#pragma unroll
            for (int gi = 0; gi < 8; gi++)
#pragma unroll
                for (int j = 0; j < 4; j++)
                    ffma2(acc[gi][j], hh[j], wd[gi]);
        }
        __syncthreads();
    }
#pragma unroll
    for (int gi = 0; gi < 8; gi++) {
        int g = gt * 128 + gy * 8 + gi;
        float bias = __ldg(b_ih + g) + __ldg(b_hh + g);
        float2 u0 = unpack2(acc[gi][0]);
        float2 u1 = unpack2(acc[gi][1]);
        float2 u2 = unpack2(acc[gi][2]);
        float2 u3 = unpack2(acc[gi][3]);
        float* op = g_pre0 + (size_t)t * (Gn * Bn) + (size_t)g * Bn + bx * 8;
        *reinterpret_cast<float4*>(op) =
            make_float4(u0.x + bias, u0.y + bias, u1.x + bias, u1.y + bias);
        *reinterpret_cast<float4*>(op + 4) =
            make_float4(u2.x + bias, u2.y + bias, u3.x + bias, u3.y + bias);
    }
}

// ---------------------------------------------------------------------------
// Persistent skewed recurrence. 256 CTAs x 256 threads (2 CTAs/SM).
// CTA: bq = blk&3 (batch quarter 32), cg = blk>>2 (4 h-cols, both layers).
// Warps (8): bsel = w&1 (16-batch), kshi = w>>1 (64-K slice).
// Lanes: cs = lane&7 (2 col-pairs), kslo = lane>>3 (16-K sub-slice).
// Dual staging buffers (A & B committed up front, swizzled, pad-free);
// partials overlay stage-A region after phases complete.
// smem: WA 32768 | WB 16384 | stageA 32768 | stageB 32768 -> 114688 (14 gran)
// ---------------------------------------------------------------------------
#define SM_WA    0
#define SM_WB    32768
#define SM_STAGE 49152
#define SM_STB_OFF 32768
#define SMEM_TOTAL 114688

__global__ __launch_bounds__(256, 2) void lstm_persistent(
    const float* __restrict__ W_ih, const float* __restrict__ W_hh,
    const float* __restrict__ b_ih, const float* __restrict__ b_hh,
    float* __restrict__ out)
{
    extern __shared__ __align__(16) char smraw[];
    char* smWA   = smraw + SM_WA;
    char* smWB   = smraw + SM_WB;
    char* stage  = smraw + SM_STAGE;          // stage A; stage B = +32768
    char* partc  = smraw + SM_STAGE;          // partials overlay stage A

    const int tid  = threadIdx.x;
    const int blk  = blockIdx.x;
    const int bq   = blk & 3;
    const int cg   = blk >> 2;
    const int w    = tid >> 5;
    const int lane = tid & 31;
    const int bsel = w & 1;
    const int kshi = w >> 1;          // 0..3
    const int cs   = lane & 7;
    const int kslo = lane >> 3;       // 0..3

    // ---- weights into smem (plain floats, once) ----
    {
        int p  = tid & 15;
        int kg = tid >> 4;            // 0..15 -> 16 k each
        int gc = (p >> 2) * Hn + cg * 4 + (p & 3);
        const float* wh0 = W_hh + (size_t)gc * Hn;
        const float* wi1 = W_ih + (size_t)Gn * Hn + (size_t)gc * Hn;
        float* WA = reinterpret_cast<float*>(smWA);
#pragma unroll
        for (int j = 0; j < 16; j++) {
            int k = kg * 16 + j;
            WA[k * 32 + p * 2 + 0] = __ldg(wh0 + k);
            WA[k * 32 + p * 2 + 1] = __ldg(wi1 + k);
        }
        int c   = tid & 7;
        int kg2 = tid >> 3;           // 0..31 -> 8 k each
        int gcA = ((2 * c) >> 2) * Hn + cg * 4 + ((2 * c) & 3);
        int gcB = ((2 * c + 1) >> 2) * Hn + cg * 4 + ((2 * c + 1) & 3);
        const float* wh1a = W_hh + (size_t)Gn * Hn + (size_t)gcA * Hn;
        const float* wh1b = W_hh + (size_t)Gn * Hn + (size_t)gcB * Hn;
        float* WB = reinterpret_cast<float*>(smWB);
#pragma unroll
        for (int j = 0; j < 8; j++) {
            int k = kg2 * 8 + j;
            WB[k * 16 + c * 2 + 0] = __ldg(wh1a + k);
            WB[k * 16 + c * 2 + 1] = __ldg(wh1b + k);
        }
    }
    // elementwise identity (EW0: tid<128, EW1: tid>=128)
    const int hcl = (tid >> 5) & 3;
    const int bl  = tid & 31;
    const int hcol = cg * 4 + hcl;
    const int b = bq * 32 + bl;
    float b1s[4];
#pragma unroll
    for (int g = 0; g < 4; g++)
        b1s[g] = __ldg(b_ih + Gn + g * Hn + hcol) + __ldg(b_hh + Gn + g * Hn + hcol);

    // per-warp staging base (4 blocks of 1024B, seg-swizzled, no pads)
    char* myst = stage + w * 4096;

    // zero init h ping-pong buffers (256 CTAs x 256 threads = 65536)
    {
        int idx = blk * 256 + tid;
        reinterpret_cast<float*>(g_h0)[idx] = 0.f;
        reinterpret_cast<float*>(g_h1)[idx] = 0.f;
    }
    float creg = 0.f;

    const size_t OUT_H = (size_t)Tn * Bn * Hn;
    const size_t OUT_C = OUT_H + 2 * (size_t)Bn * Hn;

    grid_barrier();   // init + weights visible

    for (int i = 0; i <= Tn; i++) {
        const int rslot = (i & 1) ^ 1;
        const int wslot = i & 1;
        const float* hA = g_h0[rslot];
        const float* hB = g_h1[rslot];

        // ===== stage A (h0) and stage B (h1), both up front, swizzled =====
#pragma unroll
        for (int j = 0; j < 8; j++) {
            int f = lane + j * 32;
            int ksb = f >> 6, rem = f & 63;
            int krow = rem >> 2, seg = rem & 3;
            int k = kshi * 64 + ksb * 16 + krow;
            size_t so = (size_t)k * Bn + bq * 32 + bsel * 16 + seg * 4;
            cp16(myst + ksb * 1024 + krow * 64 + (((seg + ksb) & 3) << 4), hA + so);
        }
        asm volatile("cp.async.commit_group;");
#pragma unroll
        for (int j = 0; j < 8; j++) {
            int f = lane + j * 32;
            int ksb = f >> 6, rem = f & 63;
            int krow = rem >> 2, seg = rem & 3;
            int k = kshi * 64 + ksb * 16 + krow;
            size_t so = (size_t)k * Bn + bq * 32 + bsel * 16 + seg * 4;
            cp16(myst + SM_STB_OFF + ksb * 1024 + krow * 64 + (((seg + ksb) & 3) << 4),
                 hB + so);
        }
        asm volatile("cp.async.commit_group;");

        // prefetch pre0 gates (EW0 operand) while staging flies
        float pg[4] = {0.f, 0.f, 0.f, 0.f};
        if (tid < 128 && i < Tn) {
            const float* pb = g_pre0 + (size_t)i * (Gn * Bn);
#pragma unroll
            for (int g = 0; g < 4; g++)
                pg[g] = __ldg(pb + (size_t)(g * Hn + hcol) * Bn + b);
        }

        u64t acc[4][8];
#pragma unroll
        for (int r = 0; r < 4; r++)
#pragma unroll
            for (int j = 0; j < 8; j++) acc[r][j] = 0ull;

        // swizzled read pointers: logical seg s lives at phys ((s+kslo)&3)
        const char* p0 = myst + kslo * 1024 + (((0 + kslo) & 3) << 4);
        const char* p1 = myst + kslo * 1024 + (((1 + kslo) & 3) << 4);
        const char* p2 = myst + kslo * 1024 + (((2 + kslo) & 3) << 4);
        const char* p3 = myst + kslo * 1024 + (((3 + kslo) & 3) << 4);

        asm volatile("cp.async.wait_group 1;");
        __syncwarp();
        // ===== phase A: L0-rec + L1-input on h0 slice =====
        {
            const char* wp = smWA + (size_t)(kshi * 64 + kslo * 16) * 128 + cs * 16;
#pragma unroll
            for (int u = 0; u < 16; u++) {
                ulonglong2 h0v = *reinterpret_cast<const ulonglong2*>(p0 + u * 64);
                ulonglong2 h1v = *reinterpret_cast<const ulonglong2*>(p1 + u * 64);
                ulonglong2 h2v = *reinterpret_cast<const ulonglong2*>(p2 + u * 64);
                ulonglong2 h3v = *reinterpret_cast<const ulonglong2*>(p3 + u * 64);
                float4 wv = *reinterpret_cast<const float4*>(wp);
                u64t w0a = dup2(wv.x), w1a = dup2(wv.y);
                u64t w0b = dup2(wv.z), w1b = dup2(wv.w);
                u64t hh[8] = {h0v.x, h0v.y, h1v.x, h1v.y, h2v.x, h2v.y, h3v.x, h3v.y};
#pragma unroll
                for (int j = 0; j < 8; j++) {
                    ffma2(acc[0][j], hh[j], w0a);
                    ffma2(acc[2][j], hh[j], w1a);
                    ffma2(acc[1][j], hh[j], w0b);
                    ffma2(acc[3][j], hh[j], w1b);
                }
                wp += 128;
            }
        }
        asm volatile("cp.async.wait_group 0;");
        __syncwarp();
        // ===== phase B: L1-rec on h1 slice (accumulate into L1 accs) =====
        {
            const char* wp = smWB + (size_t)(kshi * 64 + kslo * 16) * 64 + cs * 8;
#pragma unroll
            for (int u = 0; u < 16; u++) {
                ulonglong2 h0v = *reinterpret_cast<const ulonglong2*>(p0 + SM_STB_OFF + u * 64);
                ulonglong2 h1v = *reinterpret_cast<const ulonglong2*>(p1 + SM_STB_OFF + u * 64);
                ulonglong2 h2v = *reinterpret_cast<const ulonglong2*>(p2 + SM_STB_OFF + u * 64);
                ulonglong2 h3v = *reinterpret_cast<const ulonglong2*>(p3 + SM_STB_OFF + u * 64);
                float2 wv = *reinterpret_cast<const float2*>(wp);
                u64t w2a = dup2(wv.x), w2b = dup2(wv.y);
                u64t hh[8] = {h0v.x, h0v.y, h1v.x, h1v.y, h2v.x, h2v.y, h3v.x, h3v.y};
#pragma unroll
                for (int j = 0; j < 8; j++) {
                    ffma2(acc[2][j], hh[j], w2a);
                    ffma2(acc[3][j], hh[j], w2b);
                }
                wp += 64;
            }
        }

        // ===== in-warp reduce over kslo (xor 8, xor 16) =====
#pragma unroll
        for (int r = 0; r < 4; r++)
#pragma unroll
            for (int j = 0; j < 8; j++) {
                u64t v = acc[r][j];
                v = addx2(v, (u64t)__shfl_xor_sync(0xFFFFFFFFu, v, 8));
                v = addx2(v, (u64t)__shfl_xor_sync(0xFFFFFFFFu, v, 16));
                acc[r][j] = v;
            }
        // all warps must finish reading stage A before partials overlay it
        __syncthreads();
        if (kslo == 0) {
#pragma unroll
            for (int r = 0; r < 4; r++) {
                int row = (r < 2) ? (2 * cs + r) : (16 + 2 * cs + (r - 2));
                char* pb = partc + row * 528 + kshi * 128 + bsel * 64;
                reinterpret_cast<ulonglong2*>(pb)[0] = make_ulonglong2(acc[r][0], acc[r][1]);
                reinterpret_cast<ulonglong2*>(pb)[1] = make_ulonglong2(acc[r][2], acc[r][3]);
                reinterpret_cast<ulonglong2*>(pb)[2] = make_ulonglong2(acc[r][4], acc[r][5]);
                reinterpret_cast<ulonglong2*>(pb)[3] = make_ulonglong2(acc[r][6], acc[r][7]);
            }
        }
        __syncthreads();

        // ===== elementwise (sum 4 kshi partials) =====
        if (tid < 128) {
            if (i < Tn) {
                float s[4];
#pragma unroll
                for (int g = 0; g < 4; g++) {
                    const float* pr = reinterpret_cast<const float*>(
                        partc + (g * 4 + hcl) * 528 + bl * 4);
                    s[g] = pg[g] + pr[0] + pr[32] + pr[64] + pr[96];
                }
                float cn = fsig(s[1]) * creg + fsig(s[0]) * ftanh2(s[2]);
                creg = cn;
                float hn = fsig(s[3]) * ftanh2(cn);
                __stcg(&g_h0[wslot][hcol * Bn + b], hn);
                if (i == Tn - 1) {
                    out[OUT_H + (size_t)b * Hn + hcol] = hn;
                    out[OUT_C + (size_t)b * Hn + hcol] = cn;
                }
            }
        } else {
            if (i >= 1) {
                const int t1 = i - 1;
                float s[4];
#pragma unroll
                for (int g = 0; g < 4; g++) {
                    const float* pr = reinterpret_cast<const float*>(
                        partc + (16 + g * 4 + hcl) * 528 + bl * 4);
                    s[g] = b1s[g] + pr[0] + pr[32] + pr[64] + pr[96];
                }
                float cn = fsig(s[1]) * creg + fsig(s[0]) * ftanh2(s[2]);
                creg = cn;
                float hn = fsig(s[3]) * ftanh2(cn);
                __stcg(&g_h1[wslot][hcol * Bn + b], hn);
                out[(size_t)t1 * (Bn * Hn) + (size_t)b * Hn + hcol] = hn;
                if (i == Tn) {
                    out[OUT_H + (size_t)Bn * Hn + (size_t)b * Hn + hcol] = hn;
                    out[OUT_C + (size_t)Bn * Hn + (size_t)b * Hn + hcol] = cn;
                }
            }
        }
        grid_barrier();
    }
}

extern "C" void kernel_launch(void* const* d_in, const int* in_sizes, int n_in,
                              void* d_out, int out_size) {
    (void)in_sizes; (void)n_in; (void)out_size;
    const float* x    = (const float*)d_in[0];
    const float* W_ih = (const float*)d_in[1];
    const float* W_hh = (const float*)d_in[2];
    const float* b_ih = (const float*)d_in[3];
    const float* b_hh = (const float*)d_in[4];
    float* out = (float*)d_out;

    cudaFuncSetAttribute(precompute_kernel,
                         cudaFuncAttributeMaxDynamicSharedMemorySize, PRE_SMEM);
    cudaFuncSetAttribute(lstm_persistent,
                         cudaFuncAttributeMaxDynamicSharedMemorySize, SMEM_TOTAL);

    dim3 gPre(8, 512);
    precompute_kernel<<<gPre, 256, PRE_SMEM>>>(x, W_ih, b_ih, b_hh);
    lstm_persistent<<<NBLK, 256, SMEM_TOTAL>>>(W_ih, W_hh, b_ih, b_hh, out);
}